// round 10
// baseline (speedup 1.0000x reference)
#include <cuda_runtime.h>
#include <cuda_bf16.h>
#include <math.h>
#include <stdint.h>

#define BB 4
#define SS 2048
#define DM 1024
#define NH 16
#define HD 64
#define MT (BB*SS)          // 8192 rows
#define BSD (MT*DM)         // 8,388,608 elements per matrix

// Scratch (static device globals)
static __device__ __align__(16) __nv_bfloat16 g_xhi[BSD];   // x hi / attn-out hi
static __device__ __align__(16) __nv_bfloat16 g_xlo[BSD];
static __device__ __align__(16) __nv_bfloat16 g_whi[4*DM*DM];
static __device__ __align__(16) __nv_bfloat16 g_wlo[4*DM*DM];
static __device__ __align__(16) __nv_bfloat16 g_qhi[BSD], g_qlo[BSD];
static __device__ __align__(16) __nv_bfloat16 g_khi[BSD], g_klo[BSD];
static __device__ __align__(16) __nv_bfloat16 g_vhi[BSD], g_vlo[BSD];

// ---------------------------------------------------------------------------
// PTX helpers (compute_103 baseline: mma.sync / ldmatrix / cp.async)
// ---------------------------------------------------------------------------
__device__ __forceinline__ uint32_t smem_u32(const void* p) {
    uint32_t a;
    asm("{ .reg .u64 t; cvta.to.shared.u64 t, %1; cvt.u32.u64 %0, t; }" : "=r"(a) : "l"(p));
    return a;
}
__device__ __forceinline__ void cp16(uint32_t saddr, const void* g) {
    asm volatile("cp.async.cg.shared.global [%0], [%1], 16;" :: "r"(saddr), "l"(g) : "memory");
}
__device__ __forceinline__ void cp_commit() {
    asm volatile("cp.async.commit_group;" ::: "memory");
}
template <int N>
__device__ __forceinline__ void cp_wait() {
    asm volatile("cp.async.wait_group %0;" :: "n"(N) : "memory");
}
__device__ __forceinline__ void ldsm4(uint32_t addr, uint32_t r[4]) {
    asm volatile("ldmatrix.sync.aligned.m8n8.x4.shared.b16 {%0,%1,%2,%3}, [%4];"
                 : "=r"(r[0]), "=r"(r[1]), "=r"(r[2]), "=r"(r[3]) : "r"(addr));
}
__device__ __forceinline__ void ldsm4t(uint32_t addr, uint32_t r[4]) {
    asm volatile("ldmatrix.sync.aligned.m8n8.x4.trans.shared.b16 {%0,%1,%2,%3}, [%4];"
                 : "=r"(r[0]), "=r"(r[1]), "=r"(r[2]), "=r"(r[3]) : "r"(addr));
}
__device__ __forceinline__ void mma16816(float c[4], const uint32_t a[4],
                                         uint32_t b0, uint32_t b1) {
    asm volatile(
        "mma.sync.aligned.m16n8k16.row.col.f32.bf16.bf16.f32 "
        "{%0,%1,%2,%3}, {%4,%5,%6,%7}, {%8,%9}, {%0,%1,%2,%3};"
        : "+f"(c[0]), "+f"(c[1]), "+f"(c[2]), "+f"(c[3])
        : "r"(a[0]), "r"(a[1]), "r"(a[2]), "r"(a[3]), "r"(b0), "r"(b1));
}
#define SWZ(off) ((off) ^ (((off) >> 3) & 0x70))

__device__ __forceinline__ uint32_t pack_bf16(float x, float y) {
    __nv_bfloat162 t(__float2bfloat16_rn(x), __float2bfloat16_rn(y));
    return *(uint32_t*)&t;
}

// ---------------------------------------------------------------------------
// fp32 -> bf16 (hi, lo) split conversion for x.  n4 = elems/4.
// ---------------------------------------------------------------------------
__global__ void conv_hilo(const float4* __restrict__ src,
                          __nv_bfloat16* __restrict__ hi,
                          __nv_bfloat16* __restrict__ lo, int n4)
{
    int i = blockIdx.x * blockDim.x + threadIdx.x;
    if (i >= n4) return;
    float4 v = src[i];
    float f[4] = {v.x, v.y, v.z, v.w};
    __nv_bfloat162 h2[2], l2[2];
    #pragma unroll
    for (int j = 0; j < 2; j++) {
        __nv_bfloat16 h0 = __float2bfloat16_rn(f[2*j]);
        __nv_bfloat16 h1 = __float2bfloat16_rn(f[2*j+1]);
        __nv_bfloat16 l0 = __float2bfloat16_rn(f[2*j]   - __bfloat162float(h0));
        __nv_bfloat16 l1 = __float2bfloat16_rn(f[2*j+1] - __bfloat162float(h1));
        h2[j] = __nv_bfloat162(h0, h1);
        l2[j] = __nv_bfloat162(l0, l1);
    }
    *(uint2*)(hi + 4*(size_t)i) = *(uint2*)h2;
    *(uint2*)(lo + 4*(size_t)i) = *(uint2*)l2;
}

// All 4 weight matrices in one launch (blockIdx.y selects the matrix).
__global__ void conv_w(const float4* __restrict__ w0, const float4* __restrict__ w1,
                       const float4* __restrict__ w2, const float4* __restrict__ w3)
{
    const int z = blockIdx.y;
    const float4* src = (z == 0) ? w0 : (z == 1) ? w1 : (z == 2) ? w2 : w3;
    int i = blockIdx.x * blockDim.x + threadIdx.x;          // < DM*DM/4
    float4 v = src[i];
    float f[4] = {v.x, v.y, v.z, v.w};
    __nv_bfloat162 h2[2], l2[2];
    #pragma unroll
    for (int j = 0; j < 2; j++) {
        __nv_bfloat16 h0 = __float2bfloat16_rn(f[2*j]);
        __nv_bfloat16 h1 = __float2bfloat16_rn(f[2*j+1]);
        __nv_bfloat16 l0 = __float2bfloat16_rn(f[2*j]   - __bfloat162float(h0));
        __nv_bfloat16 l1 = __float2bfloat16_rn(f[2*j+1] - __bfloat162float(h1));
        h2[j] = __nv_bfloat162(h0, h1);
        l2[j] = __nv_bfloat162(l0, l1);
    }
    size_t o = (size_t)z * DM * DM + 4*(size_t)i;
    *(uint2*)(g_whi + o) = *(uint2*)h2;
    *(uint2*)(g_wlo + o) = *(uint2*)l2;
}

// ---------------------------------------------------------------------------
// GEMM fragment loader (one k16 step worth of A (64 rows) and B (32 cols))
// ---------------------------------------------------------------------------
__device__ __forceinline__ void gemm_ldfrag(
    uint32_t sAh, uint32_t sAl, uint32_t sBh, uint32_t sBl,
    int wm, int wn, int a_row, int a_ku, int b_row, int b_ku, int q,
    uint32_t ah[4][4], uint32_t al[4][4], uint32_t bh[2][4], uint32_t bl[2][4])
{
    const int cu = q * 2;
    #pragma unroll
    for (int i = 0; i < 4; i++) {
        uint32_t off = SWZ((uint32_t)((wm + i*16 + a_row) * 128 + (cu + a_ku) * 16));
        ldsm4(sAh + off, ah[i]);
        ldsm4(sAl + off, al[i]);
    }
    #pragma unroll
    for (int j = 0; j < 2; j++) {
        uint32_t off = SWZ((uint32_t)((wn + j*16 + b_row) * 128 + (cu + b_ku) * 16));
        ldsm4(sBh + off, bh[j]);
        ldsm4(sBl + off, bl[j]);
    }
}

// ---------------------------------------------------------------------------
// HMMA split-bf16 GEMM v3: C[m][n] = sum_k A[m][k] * W[n][k]
// 128x128 CTA tile, 256 threads (8 warps), warp tile 64x32.
// K-chunk 64, 3-stage cp.async smem pipeline + register fragment double-buffer.
// ---------------------------------------------------------------------------
#define GK_TILE   16384
#define GK_STAGE  (4*GK_TILE)
#define GK_NST    3
#define GK_SMEM   (GK_NST*GK_STAGE)     // 192KB
#define NKCH      16

template<bool ROPE>
__global__ void __launch_bounds__(256, 1) gemm_hmma(
    const __nv_bfloat16* __restrict__ Ahi, const __nv_bfloat16* __restrict__ Alo,
    const __nv_bfloat16* __restrict__ Whi, const __nv_bfloat16* __restrict__ Wlo,
    const int* __restrict__ pos, float* __restrict__ C)
{
    extern __shared__ char smem[];
    const uint32_t sbase = smem_u32(smem);
    const int tid = threadIdx.x, lane = tid & 31, wid = tid >> 5;
    const int n0 = blockIdx.x * 128, m0 = blockIdx.y * 128, z = blockIdx.z;

    const __nv_bfloat16* __restrict__ srcs[4] = {
        Ahi + (size_t)m0 * DM,
        Alo + (size_t)m0 * DM,
        Whi + (size_t)z * DM * DM + (size_t)n0 * DM,
        Wlo + (size_t)z * DM * DM + (size_t)n0 * DM };

    auto fill = [&](int st, int kt) {
        uint32_t sb = sbase + st * GK_STAGE;
        #pragma unroll
        for (int t = 0; t < 4; t++) {
            const __nv_bfloat16* s = srcs[t] + kt * 64;
            #pragma unroll
            for (int j = 0; j < 4; j++) {
                int idx = j * 256 + tid;
                int row = idx >> 3, cu = idx & 7;
                cp16(sb + t * GK_TILE + SWZ((uint32_t)(row * 128 + cu * 16)),
                     s + (size_t)row * DM + cu * 8);
            }
        }
        cp_commit();
    };

    const int wm = (wid & 1) * 64;
    const int wn = (wid >> 1) * 32;
    const int a_row = lane & 15;
    const int a_ku  = lane >> 4;
    const int b_row = ((lane >> 4) << 3) + (lane & 7);
    const int b_ku  = (lane >> 3) & 1;

    float acc[4][4][4];
    #pragma unroll
    for (int i = 0; i < 4; i++)
        #pragma unroll
        for (int j = 0; j < 4; j++)
            #pragma unroll
            for (int c = 0; c < 4; c++) acc[i][j][c] = 0.0f;

    fill(0, 0);
    fill(1, 1);

    uint32_t ah[2][4][4], al[2][4][4], bh[2][2][4], bl[2][2][4];

    int st = 0;
    #pragma unroll 1
    for (int kt = 0; kt < NKCH; kt++) {
        if (kt == NKCH - 1) cp_wait<0>(); else cp_wait<1>();
        __syncthreads();

        if (kt + 2 < NKCH) {
            int fs = st + 2; if (fs >= GK_NST) fs -= GK_NST;
            fill(fs, kt + 2);
        }

        const uint32_t sb  = sbase + st * GK_STAGE;
        const uint32_t sAh = sb, sAl = sb + GK_TILE;
        const uint32_t sBh = sb + 2*GK_TILE, sBl = sb + 3*GK_TILE;

        gemm_ldfrag(sAh, sAl, sBh, sBl, wm, wn, a_row, a_ku, b_row, b_ku, 0,
                    ah[0], al[0], bh[0], bl[0]);

        #pragma unroll
        for (int q = 0; q < 4; q++) {
            const int cur = q & 1, nxt = cur ^ 1;
            if (q < 3)
                gemm_ldfrag(sAh, sAl, sBh, sBl, wm, wn, a_row, a_ku, b_row, b_ku, q + 1,
                            ah[nxt], al[nxt], bh[nxt], bl[nxt]);
            #pragma unroll
            for (int i = 0; i < 4; i++)
                #pragma unroll
                for (int jj = 0; jj < 4; jj++) {
                    const int j16 = jj >> 1, h = (jj & 1) * 2;
                    mma16816(acc[i][jj], ah[cur][i], bh[cur][j16][h], bh[cur][j16][h+1]);
                    mma16816(acc[i][jj], ah[cur][i], bl[cur][j16][h], bl[cur][j16][h+1]);
                    mma16816(acc[i][jj], al[cur][i], bh[cur][j16][h], bh[cur][j16][h+1]);
                }
        }
        if (++st == GK_NST) st = 0;
    }

    const int er = lane >> 2;
    const int ec = (lane & 3) * 2;

    if constexpr (!ROPE) {
        #pragma unroll
        for (int i = 0; i < 4; i++)
            #pragma unroll
            for (int jj = 0; jj < 4; jj++) {
                const int row = m0 + wm + i*16 + er;
                const int col = n0 + wn + jj*8 + ec;
                *(float2*)(C + (size_t)row * DM + col)       = make_float2(acc[i][jj][0], acc[i][jj][1]);
                *(float2*)(C + (size_t)(row + 8) * DM + col) = make_float2(acc[i][jj][2], acc[i][jj][3]);
            }
    } else {
        __nv_bfloat16* hiA = (z == 0) ? g_qhi : (z == 1 ? g_khi : g_vhi);
        __nv_bfloat16* loA = (z == 0) ? g_qlo : (z == 1 ? g_klo : g_vlo);
        float ifr[4];
        if (z < 2) {
            #pragma unroll
            for (int jj = 0; jj < 4; jj++) {
                int dcol = (wn & 32) + jj*8 + ec;        // even d index within head
                ifr[jj] = __expf(-(float)dcol * (9.210340371976184f / 64.0f));
            }
        }
        #pragma unroll
        for (int i = 0; i < 4; i++) {
            #pragma unroll
            for (int half = 0; half < 2; half++) {
                const int row = m0 + wm + i*16 + er + half*8;   // global m = b*SS+s
                const int b = row >> 11, s = row & (SS - 1);
                int ps = 0;
                if (z < 2) ps = pos[row];
                #pragma unroll
                for (int jj = 0; jj < 4; jj++) {
                    const int col = n0 + wn + jj*8 + ec;
                    float e = acc[i][jj][half*2], o = acc[i][jj][half*2+1];
                    if (z < 2) {
                        float sn, cs;
                        sincosf((float)ps * ifr[jj], &sn, &cs);
                        float e2 = e * cs - o * sn;
                        o        = e * sn + o * cs;
                        e = e2;
                    }
                    float eh = __bfloat162float(__float2bfloat16_rn(e));
                    float oh = __bfloat162float(__float2bfloat16_rn(o));
                    const int h = col >> 6, d = col & 63;
                    size_t di = ((size_t)((b << 4) + h) * SS + s) * HD + d;
                    *(uint32_t*)(hiA + di) = pack_bf16(eh, oh);
                    *(uint32_t*)(loA + di) = pack_bf16(e - eh, o - oh);
                }
            }
        }
    }
}

// ---------------------------------------------------------------------------
// Attention fragment loaders
// ---------------------------------------------------------------------------
__device__ __forceinline__ void attn_ldK(uint32_t sKh, uint32_t sKl,
                                         int b_row, int b_ku, int st,
                                         uint32_t kh[4][4], uint32_t kl[4][4])
{
    const int cu = st * 2;
    #pragma unroll
    for (int jn = 0; jn < 4; jn++) {
        uint32_t off = SWZ((uint32_t)((jn*16 + b_row) * 128 + (cu + b_ku) * 16));
        ldsm4(sKh + off, kh[jn]);
        ldsm4(sKl + off, kl[jn]);
    }
}
__device__ __forceinline__ void attn_ldV(uint32_t sVh, uint32_t sVl,
                                         int v_row, int v_cb, int kk,
                                         uint32_t vh[4][4], uint32_t vl[4][4])
{
    #pragma unroll
    for (int jv = 0; jv < 4; jv++) {
        uint32_t off = SWZ((uint32_t)((kk*16 + v_row) * 128 + jv*32 + v_cb));
        ldsm4t(sVh + off, vh[jv]);
        ldsm4t(sVl + off, vl[jv]);
    }
}

// ---------------------------------------------------------------------------
// HMMA flash attention v2: 128 query rows per CTA, 8 warps (16 rows each),
// key tiles of 64.  3-stage KV smem pipeline + register fragment double-buffer.
// ---------------------------------------------------------------------------
#define AQ_TILE 16384
#define AKV_TILE 8192
#define AKV_STAGE (4*AKV_TILE)
#define AKV_NST 3
#define ASMEM (2*AQ_TILE + AKV_NST*AKV_STAGE)   // 128KB

__global__ void __launch_bounds__(256, 1) attn_hmma()
{
    extern __shared__ char smem[];
    const uint32_t sbase = smem_u32(smem);
    const int tid = threadIdx.x, lane = tid & 31, wid = tid >> 5;
    const int qt = (int)gridDim.x - 1 - (int)blockIdx.x;
    const int bh = blockIdx.y;
    const int s0 = qt * 128;
    const int nkt = 2 * qt + 2;

    const size_t bhoff = (size_t)bh * SS * HD;
    const __nv_bfloat16* Qh = g_qhi + bhoff + (size_t)s0 * HD;
    const __nv_bfloat16* Ql = g_qlo + bhoff + (size_t)s0 * HD;
    const __nv_bfloat16* kvsrc[4] = { g_khi + bhoff, g_klo + bhoff,
                                      g_vhi + bhoff, g_vlo + bhoff };

    const uint32_t sQ  = sbase;
    const uint32_t sKV = sbase + 2*AQ_TILE;

    {
        #pragma unroll
        for (int j = 0; j < 4; j++) {
            int idx = j * 256 + tid;
            int row = idx >> 3, cu = idx & 7;
            uint32_t off = SWZ((uint32_t)(row * 128 + cu * 16));
            cp16(sQ + off,           Qh + (size_t)row * HD + cu * 8);
            cp16(sQ + AQ_TILE + off, Ql + (size_t)row * HD + cu * 8);
        }
        cp_commit();
    }
    auto fill_kv = [&](int st, int kb) {
        uint32_t sb = sKV + st * AKV_STAGE;
        #pragma unroll
        for (int t = 0; t < 4; t++) {
            const __nv_bfloat16* s = kvsrc[t] + (size_t)kb * 64 * HD;
            #pragma unroll
            for (int r = 0; r < 2; r++) {
                int idx = r * 256 + tid;
                int row = idx >> 3, cu = idx & 7;
                cp16(sb + t * AKV_TILE + SWZ((uint32_t)(row * 128 + cu * 16)),
                     s + (size_t)row * HD + cu * 8);
            }
        }
        cp_commit();
    };
    fill_kv(0, 0);
    fill_kv(1, 1);

    cp_wait<2>();
    __syncthreads();
    uint32_t qh[4][4], ql[4][4];
    {
        const int a_row = lane & 15, a_ku = lane >> 4;
        #pragma unroll
        for (int st = 0; st < 4; st++) {
            uint32_t off = SWZ((uint32_t)((wid*16 + a_row) * 128 + (st*2 + a_ku) * 16));
            ldsm4(sQ + off, qh[st]);
            ldsm4(sQ + AQ_TILE + off, ql[st]);
        }
    }

    float o_acc[8][4];
    #pragma unroll
    for (int jj = 0; jj < 8; jj++)
        #pragma unroll
        for (int c = 0; c < 4; c++) o_acc[jj][c] = 0.0f;
    float row_max[2] = {-1e30f, -1e30f}, row_l[2] = {0.0f, 0.0f};

    const int b_row = ((lane >> 4) << 3) + (lane & 7);
    const int b_ku  = (lane >> 3) & 1;
    const int v_row = lane & 15;
    const int v_cb  = ((lane >> 4) << 3) * 2;
    const float scale = 0.125f;

    int stg = 0;
    #pragma unroll 1
    for (int kb = 0; kb < nkt; kb++) {
        if (kb == nkt - 1) cp_wait<0>(); else cp_wait<1>();
        __syncthreads();

        if (kb + 2 < nkt) {
            int fs = stg + 2; if (fs >= AKV_NST) fs -= AKV_NST;
            fill_kv(fs, kb + 2);
        }

        const uint32_t sb = sKV + stg * AKV_STAGE;
        const uint32_t sKh = sb, sKl = sb + AKV_TILE;
        const uint32_t sVh = sb + 2*AKV_TILE, sVl = sb + 3*AKV_TILE;

        // ---- S = Q K^T with K fragment double-buffer ----
        float sacc[8][4];
        #pragma unroll
        for (int jj = 0; jj < 8; jj++)
            #pragma unroll
            for (int c = 0; c < 4; c++) sacc[jj][c] = 0.0f;

        uint32_t kh[2][4][4], kl[2][4][4];
        attn_ldK(sKh, sKl, b_row, b_ku, 0, kh[0], kl[0]);
        #pragma unroll
        for (int st = 0; st < 4; st++) {
            const int cur = st & 1, nxt = cur ^ 1;
            if (st < 3)
                attn_ldK(sKh, sKl, b_row, b_ku, st + 1, kh[nxt], kl[nxt]);
            #pragma unroll
            for (int jj = 0; jj < 8; jj++) {
                const int j16 = jj >> 1, h = (jj & 1) * 2;
                mma16816(sacc[jj], qh[st], kh[cur][j16][h], kh[cur][j16][h+1]);
                mma16816(sacc[jj], qh[st], kl[cur][j16][h], kl[cur][j16][h+1]);
                mma16816(sacc[jj], ql[st], kh[cur][j16][h], kh[cur][j16][h+1]);
            }
        }

        // ---- prefetch V fragments for kk=0 (overlaps softmax ALU) ----
        uint32_t vh[2][4][4], vl[2][4][4];
        attn_ldV(sVh, sVl, v_row, v_cb, 0, vh[0], vl[0]);

        // ---- online softmax ----
        const bool tmask = (kb >= 2 * qt);
        #pragma unroll
        for (int rh = 0; rh < 2; rh++) {
            const int grow = s0 + wid*16 + (lane >> 2) + rh*8;
            float mx = -1e30f;
            #pragma unroll
            for (int jj = 0; jj < 8; jj++)
                #pragma unroll
                for (int dc = 0; dc < 2; dc++) {
                    float v = sacc[jj][rh*2+dc] * scale;
                    if (tmask && (kb*64 + jj*8 + 2*(lane&3) + dc > grow)) v = -1e30f;
                    sacc[jj][rh*2+dc] = v;
                    mx = fmaxf(mx, v);
                }
            mx = fmaxf(mx, __shfl_xor_sync(0xffffffffu, mx, 1));
            mx = fmaxf(mx, __shfl_xor_sync(0xffffffffu, mx, 2));
            float mnew = fmaxf(row_max[rh], mx);
            float corr = __expf(row_max[rh] - mnew);
            row_max[rh] = mnew;
            float sum = 0.0f;
            #pragma unroll
            for (int jj = 0; jj < 8; jj++)
                #pragma unroll
                for (int dc = 0; dc < 2; dc++) {
                    float pv = __expf(sacc[jj][rh*2+dc] - mnew);
                    sacc[jj][rh*2+dc] = pv;
                    sum += pv;
                }
            sum += __shfl_xor_sync(0xffffffffu, sum, 1);
            sum += __shfl_xor_sync(0xffffffffu, sum, 2);
            row_l[rh] = row_l[rh] * corr + sum;
            #pragma unroll
            for (int jj = 0; jj < 8; jj++) {
                o_acc[jj][rh*2]   *= corr;
                o_acc[jj][rh*2+1] *= corr;
            }
        }

        // ---- O += P V with V fragment double-buffer ----
        #pragma unroll
        for (int kk = 0; kk < 4; kk++) {
            const int cur = kk & 1, nxt = cur ^ 1;
            if (kk < 3)
                attn_ldV(sVh, sVl, v_row, v_cb, kk + 1, vh[nxt], vl[nxt]);
            uint32_t ph[4], pl[4];
            #pragma unroll
            for (int u = 0; u < 4; u++) {
                const int jj = 2*kk + (u >> 1), cb = (u & 1) * 2;
                float x = sacc[jj][cb], y = sacc[jj][cb+1];
                float hx = __bfloat162float(__float2bfloat16_rn(x));
                float hy = __bfloat162float(__float2bfloat16_rn(y));
                ph[u] = pack_bf16(hx, hy);
                pl[u] = pack_bf16(x - hx, y - hy);
            }
            #pragma unroll
            for (int jj = 0; jj < 8; jj++) {
                const int j16 = jj >> 1, h = (jj & 1) * 2;
                mma16816(o_acc[jj], ph, vh[cur][j16][h], vh[cur][j16][h+1]);
                mma16816(o_acc[jj], ph, vl[cur][j16][h], vl[cur][j16][h+1]);
                mma16816(o_acc[jj], pl, vh[cur][j16][h], vh[cur][j16][h+1]);
            }
        }
        if (++stg == AKV_NST) stg = 0;
    }

    const int b = bh >> 4, h = bh & 15;
    const float inv0 = 1.0f / row_l[0], inv1 = 1.0f / row_l[1];
    #pragma unroll
    for (int jj = 0; jj < 8; jj++) {
        #pragma unroll
        for (int rh = 0; rh < 2; rh++) {
            const int row = s0 + wid*16 + (lane >> 2) + rh*8;
            const int d   = jj*8 + 2*(lane & 3);
            const float inv = rh ? inv1 : inv0;
            float x = o_acc[jj][rh*2] * inv, y = o_acc[jj][rh*2+1] * inv;
            float hx = __bfloat162float(__float2bfloat16_rn(x));
            float hy = __bfloat162float(__float2bfloat16_rn(y));
            size_t di = ((size_t)(b * SS + row)) * DM + h * HD + d;
            *(uint32_t*)(g_xhi + di) = pack_bf16(hx, hy);
            *(uint32_t*)(g_xlo + di) = pack_bf16(x - hx, y - hy);
        }
    }
}

// ---------------------------------------------------------------------------
extern "C" void kernel_launch(void* const* d_in, const int* in_sizes, int n_in,
                              void* d_out, int out_size)
{
    const float* x  = (const float*)d_in[0];
    const int*  pos = (const int*)  d_in[1];
    const float* wq = (const float*)d_in[2];
    const float* wk = (const float*)d_in[3];
    const float* wv = (const float*)d_in[4];
    const float* wo = (const float*)d_in[5];
    float* out = (float*)d_out;

    void* p;
    cudaGetSymbolAddress(&p, g_xhi);   __nv_bfloat16* xhi = (__nv_bfloat16*)p;
    cudaGetSymbolAddress(&p, g_xlo);   __nv_bfloat16* xlo = (__nv_bfloat16*)p;
    cudaGetSymbolAddress(&p, g_whi);   __nv_bfloat16* whi = (__nv_bfloat16*)p;
    cudaGetSymbolAddress(&p, g_wlo);   __nv_bfloat16* wlo = (__nv_bfloat16*)p;

    cudaFuncSetAttribute(gemm_hmma<true>,  cudaFuncAttributeMaxDynamicSharedMemorySize, GK_SMEM);
    cudaFuncSetAttribute(gemm_hmma<false>, cudaFuncAttributeMaxDynamicSharedMemorySize, GK_SMEM);
    cudaFuncSetAttribute(attn_hmma, cudaFuncAttributeMaxDynamicSharedMemorySize, ASMEM);

    // 0) split-convert x and weights to bf16 hi/lo
    conv_hilo<<<(BSD/4 + 255)/256, 256>>>((const float4*)x, xhi, xlo, BSD/4);
    conv_w<<<dim3(DM*DM/4/256, 4), 256>>>((const float4*)wq, (const float4*)wk,
                                          (const float4*)wv, (const float4*)wo);

    // 1) q,k,v = x @ {wq,wk,wv}^T with fused RoPE + head split -> g_{q,k,v}{hi,lo}
    gemm_hmma<true><<<dim3(DM/128, MT/128, 3), 256, GK_SMEM>>>(xhi, xlo, whi, wlo, pos, nullptr);

    // 2) HMMA flash attention -> g_xhi/g_xlo (bf16 hi/lo, [b,s,D])
    attn_hmma<<<dim3(SS/128, BB*NH), 256, ASMEM>>>();

    // 3) out = attn @ wo^T
    gemm_hmma<false><<<dim3(DM/128, MT/128, 1), 256, GK_SMEM>>>(
        xhi, xlo, whi + 3*(size_t)DM*DM, wlo + 3*(size_t)DM*DM, nullptr, out);
}

// round 11
// speedup vs baseline: 1.0943x; 1.0943x over previous
#include <cuda_runtime.h>
#include <cuda_bf16.h>
#include <cuda_fp16.h>
#include <math.h>
#include <stdint.h>

#define BB 4
#define SS 2048
#define DM 1024
#define NH 16
#define HD 64
#define MT (BB*SS)          // 8192 rows
#define BSD (MT*DM)         // 8,388,608 elements per matrix

// Scratch (static device globals)
static __device__ __align__(16) __nv_bfloat16 g_xhi[BSD];   // x hi / attn-out hi
static __device__ __align__(16) __nv_bfloat16 g_xlo[BSD];
static __device__ __align__(16) __nv_bfloat16 g_whi[4*DM*DM];
static __device__ __align__(16) __nv_bfloat16 g_wlo[4*DM*DM];
static __device__ __align__(16) __nv_bfloat16 g_qhi[BSD], g_qlo[BSD];
static __device__ __align__(16) __nv_bfloat16 g_khi[BSD], g_klo[BSD];
static __device__ __align__(16) __half        g_vhi[BSD], g_vlo[BSD];   // V in fp16 hi/lo

// ---------------------------------------------------------------------------
// PTX helpers (compute_103 baseline: mma.sync / ldmatrix / cp.async)
// ---------------------------------------------------------------------------
__device__ __forceinline__ uint32_t smem_u32(const void* p) {
    uint32_t a;
    asm("{ .reg .u64 t; cvta.to.shared.u64 t, %1; cvt.u32.u64 %0, t; }" : "=r"(a) : "l"(p));
    return a;
}
__device__ __forceinline__ void cp16(uint32_t saddr, const void* g) {
    asm volatile("cp.async.cg.shared.global [%0], [%1], 16;" :: "r"(saddr), "l"(g) : "memory");
}
__device__ __forceinline__ void cp_commit() {
    asm volatile("cp.async.commit_group;" ::: "memory");
}
template <int N>
__device__ __forceinline__ void cp_wait() {
    asm volatile("cp.async.wait_group %0;" :: "n"(N) : "memory");
}
__device__ __forceinline__ void ldsm4(uint32_t addr, uint32_t r[4]) {
    asm volatile("ldmatrix.sync.aligned.m8n8.x4.shared.b16 {%0,%1,%2,%3}, [%4];"
                 : "=r"(r[0]), "=r"(r[1]), "=r"(r[2]), "=r"(r[3]) : "r"(addr));
}
__device__ __forceinline__ void ldsm4t(uint32_t addr, uint32_t r[4]) {
    asm volatile("ldmatrix.sync.aligned.m8n8.x4.trans.shared.b16 {%0,%1,%2,%3}, [%4];"
                 : "=r"(r[0]), "=r"(r[1]), "=r"(r[2]), "=r"(r[3]) : "r"(addr));
}
__device__ __forceinline__ void mma16816(float c[4], const uint32_t a[4],
                                         uint32_t b0, uint32_t b1) {
    asm volatile(
        "mma.sync.aligned.m16n8k16.row.col.f32.bf16.bf16.f32 "
        "{%0,%1,%2,%3}, {%4,%5,%6,%7}, {%8,%9}, {%0,%1,%2,%3};"
        : "+f"(c[0]), "+f"(c[1]), "+f"(c[2]), "+f"(c[3])
        : "r"(a[0]), "r"(a[1]), "r"(a[2]), "r"(a[3]), "r"(b0), "r"(b1));
}
__device__ __forceinline__ void mma16816h(float c[4], const uint32_t a[4],
                                          uint32_t b0, uint32_t b1) {
    asm volatile(
        "mma.sync.aligned.m16n8k16.row.col.f32.f16.f16.f32 "
        "{%0,%1,%2,%3}, {%4,%5,%6,%7}, {%8,%9}, {%0,%1,%2,%3};"
        : "+f"(c[0]), "+f"(c[1]), "+f"(c[2]), "+f"(c[3])
        : "r"(a[0]), "r"(a[1]), "r"(a[2]), "r"(a[3]), "r"(b0), "r"(b1));
}
#define SWZ(off) ((off) ^ (((off) >> 3) & 0x70))

__device__ __forceinline__ uint32_t pack_bf16(float x, float y) {
    __nv_bfloat162 t(__float2bfloat16_rn(x), __float2bfloat16_rn(y));
    return *(uint32_t*)&t;
}
__device__ __forceinline__ uint32_t pack_f16(float x, float y) {
    __half2 t = __floats2half2_rn(x, y);
    return *(uint32_t*)&t;
}

// ---------------------------------------------------------------------------
// fp32 -> bf16 (hi, lo) split conversion for x.  n4 = elems/4.
// ---------------------------------------------------------------------------
__global__ void conv_hilo(const float4* __restrict__ src,
                          __nv_bfloat16* __restrict__ hi,
                          __nv_bfloat16* __restrict__ lo, int n4)
{
    int i = blockIdx.x * blockDim.x + threadIdx.x;
    if (i >= n4) return;
    float4 v = src[i];
    float f[4] = {v.x, v.y, v.z, v.w};
    __nv_bfloat162 h2[2], l2[2];
    #pragma unroll
    for (int j = 0; j < 2; j++) {
        __nv_bfloat16 h0 = __float2bfloat16_rn(f[2*j]);
        __nv_bfloat16 h1 = __float2bfloat16_rn(f[2*j+1]);
        __nv_bfloat16 l0 = __float2bfloat16_rn(f[2*j]   - __bfloat162float(h0));
        __nv_bfloat16 l1 = __float2bfloat16_rn(f[2*j+1] - __bfloat162float(h1));
        h2[j] = __nv_bfloat162(h0, h1);
        l2[j] = __nv_bfloat162(l0, l1);
    }
    *(uint2*)(hi + 4*(size_t)i) = *(uint2*)h2;
    *(uint2*)(lo + 4*(size_t)i) = *(uint2*)l2;
}

// All 4 weight matrices in one launch (blockIdx.y selects the matrix).
__global__ void conv_w(const float4* __restrict__ w0, const float4* __restrict__ w1,
                       const float4* __restrict__ w2, const float4* __restrict__ w3)
{
    const int z = blockIdx.y;
    const float4* src = (z == 0) ? w0 : (z == 1) ? w1 : (z == 2) ? w2 : w3;
    int i = blockIdx.x * blockDim.x + threadIdx.x;          // < DM*DM/4
    float4 v = src[i];
    float f[4] = {v.x, v.y, v.z, v.w};
    __nv_bfloat162 h2[2], l2[2];
    #pragma unroll
    for (int j = 0; j < 2; j++) {
        __nv_bfloat16 h0 = __float2bfloat16_rn(f[2*j]);
        __nv_bfloat16 h1 = __float2bfloat16_rn(f[2*j+1]);
        __nv_bfloat16 l0 = __float2bfloat16_rn(f[2*j]   - __bfloat162float(h0));
        __nv_bfloat16 l1 = __float2bfloat16_rn(f[2*j+1] - __bfloat162float(h1));
        h2[j] = __nv_bfloat162(h0, h1);
        l2[j] = __nv_bfloat162(l0, l1);
    }
    size_t o = (size_t)z * DM * DM + 4*(size_t)i;
    *(uint2*)(g_whi + o) = *(uint2*)h2;
    *(uint2*)(g_wlo + o) = *(uint2*)l2;
}

// ---------------------------------------------------------------------------
// GEMM fragment loader (one k16 step worth of A (64 rows) and B (32 cols))
// ---------------------------------------------------------------------------
__device__ __forceinline__ void gemm_ldfrag(
    uint32_t sAh, uint32_t sAl, uint32_t sBh, uint32_t sBl,
    int wm, int wn, int a_row, int a_ku, int b_row, int b_ku, int q,
    uint32_t ah[4][4], uint32_t al[4][4], uint32_t bh[2][4], uint32_t bl[2][4])
{
    const int cu = q * 2;
    #pragma unroll
    for (int i = 0; i < 4; i++) {
        uint32_t off = SWZ((uint32_t)((wm + i*16 + a_row) * 128 + (cu + a_ku) * 16));
        ldsm4(sAh + off, ah[i]);
        ldsm4(sAl + off, al[i]);
    }
    #pragma unroll
    for (int j = 0; j < 2; j++) {
        uint32_t off = SWZ((uint32_t)((wn + j*16 + b_row) * 128 + (cu + b_ku) * 16));
        ldsm4(sBh + off, bh[j]);
        ldsm4(sBl + off, bl[j]);
    }
}

// ---------------------------------------------------------------------------
// HMMA split-bf16 GEMM (round-9 proven version; only z==2 epilogue now emits
// fp16 hi/lo V).  128x128 CTA tile, 256 threads, warp tile 64x32, K-chunk 64,
// 3-stage cp.async pipeline + register fragment double-buffer.
// ---------------------------------------------------------------------------
#define GK_TILE   16384
#define GK_STAGE  (4*GK_TILE)
#define GK_NST    3
#define GK_SMEM   (GK_NST*GK_STAGE)     // 192KB
#define NKCH      16

template<bool ROPE>
__global__ void __launch_bounds__(256, 1) gemm_hmma(
    const __nv_bfloat16* __restrict__ Ahi, const __nv_bfloat16* __restrict__ Alo,
    const __nv_bfloat16* __restrict__ Whi, const __nv_bfloat16* __restrict__ Wlo,
    const int* __restrict__ pos, float* __restrict__ C)
{
    extern __shared__ char smem[];
    const uint32_t sbase = smem_u32(smem);
    const int tid = threadIdx.x, lane = tid & 31, wid = tid >> 5;
    const int n0 = blockIdx.x * 128, m0 = blockIdx.y * 128, z = blockIdx.z;

    const __nv_bfloat16* __restrict__ srcs[4] = {
        Ahi + (size_t)m0 * DM,
        Alo + (size_t)m0 * DM,
        Whi + (size_t)z * DM * DM + (size_t)n0 * DM,
        Wlo + (size_t)z * DM * DM + (size_t)n0 * DM };

    auto fill = [&](int st, int kt) {
        uint32_t sb = sbase + st * GK_STAGE;
        #pragma unroll
        for (int t = 0; t < 4; t++) {
            const __nv_bfloat16* s = srcs[t] + kt * 64;
            #pragma unroll
            for (int j = 0; j < 4; j++) {
                int idx = j * 256 + tid;
                int row = idx >> 3, cu = idx & 7;
                cp16(sb + t * GK_TILE + SWZ((uint32_t)(row * 128 + cu * 16)),
                     s + (size_t)row * DM + cu * 8);
            }
        }
        cp_commit();
    };

    const int wm = (wid & 1) * 64;
    const int wn = (wid >> 1) * 32;
    const int a_row = lane & 15;
    const int a_ku  = lane >> 4;
    const int b_row = ((lane >> 4) << 3) + (lane & 7);
    const int b_ku  = (lane >> 3) & 1;

    float acc[4][4][4];
    #pragma unroll
    for (int i = 0; i < 4; i++)
        #pragma unroll
        for (int j = 0; j < 4; j++)
            #pragma unroll
            for (int c = 0; c < 4; c++) acc[i][j][c] = 0.0f;

    fill(0, 0);
    fill(1, 1);

    uint32_t ah[2][4][4], al[2][4][4], bh[2][2][4], bl[2][2][4];

    int st = 0;
    #pragma unroll 1
    for (int kt = 0; kt < NKCH; kt++) {
        if (kt == NKCH - 1) cp_wait<0>(); else cp_wait<1>();
        __syncthreads();

        if (kt + 2 < NKCH) {
            int fs = st + 2; if (fs >= GK_NST) fs -= GK_NST;
            fill(fs, kt + 2);
        }

        const uint32_t sb  = sbase + st * GK_STAGE;
        const uint32_t sAh = sb, sAl = sb + GK_TILE;
        const uint32_t sBh = sb + 2*GK_TILE, sBl = sb + 3*GK_TILE;

        gemm_ldfrag(sAh, sAl, sBh, sBl, wm, wn, a_row, a_ku, b_row, b_ku, 0,
                    ah[0], al[0], bh[0], bl[0]);

        #pragma unroll
        for (int q = 0; q < 4; q++) {
            const int cur = q & 1, nxt = cur ^ 1;
            if (q < 3)
                gemm_ldfrag(sAh, sAl, sBh, sBl, wm, wn, a_row, a_ku, b_row, b_ku, q + 1,
                            ah[nxt], al[nxt], bh[nxt], bl[nxt]);
            #pragma unroll
            for (int i = 0; i < 4; i++)
                #pragma unroll
                for (int jj = 0; jj < 4; jj++) {
                    const int j16 = jj >> 1, h = (jj & 1) * 2;
                    mma16816(acc[i][jj], ah[cur][i], bh[cur][j16][h], bh[cur][j16][h+1]);
                    mma16816(acc[i][jj], ah[cur][i], bl[cur][j16][h], bl[cur][j16][h+1]);
                    mma16816(acc[i][jj], al[cur][i], bh[cur][j16][h], bh[cur][j16][h+1]);
                }
        }
        if (++st == GK_NST) st = 0;
    }

    const int er = lane >> 2;
    const int ec = (lane & 3) * 2;

    if constexpr (!ROPE) {
        #pragma unroll
        for (int i = 0; i < 4; i++)
            #pragma unroll
            for (int jj = 0; jj < 4; jj++) {
                const int row = m0 + wm + i*16 + er;
                const int col = n0 + wn + jj*8 + ec;
                *(float2*)(C + (size_t)row * DM + col)       = make_float2(acc[i][jj][0], acc[i][jj][1]);
                *(float2*)(C + (size_t)(row + 8) * DM + col) = make_float2(acc[i][jj][2], acc[i][jj][3]);
            }
    } else if (z == 2) {
        // V: no RoPE; head split + fp16 hi/lo
        #pragma unroll
        for (int i = 0; i < 4; i++) {
            #pragma unroll
            for (int half = 0; half < 2; half++) {
                const int row = m0 + wm + i*16 + er + half*8;   // global m = b*SS+s
                const int b = row >> 11, s = row & (SS - 1);
                #pragma unroll
                for (int jj = 0; jj < 4; jj++) {
                    const int col = n0 + wn + jj*8 + ec;
                    float e = acc[i][jj][half*2], o = acc[i][jj][half*2+1];
                    float eh = __half2float(__float2half_rn(e));
                    float oh = __half2float(__float2half_rn(o));
                    const int h = col >> 6, d = col & 63;
                    size_t di = ((size_t)((b << 4) + h) * SS + s) * HD + d;
                    *(uint32_t*)(g_vhi + di) = pack_f16(e, o);
                    *(uint32_t*)(g_vlo + di) = pack_f16(e - eh, o - oh);
                }
            }
        }
    } else {
        // Q/K: fused RoPE + head split + bf16 hi/lo
        __nv_bfloat16* hiA = (z == 0) ? g_qhi : g_khi;
        __nv_bfloat16* loA = (z == 0) ? g_qlo : g_klo;
        float ifr[4];
        #pragma unroll
        for (int jj = 0; jj < 4; jj++) {
            int dcol = (wn & 32) + jj*8 + ec;        // even d index within head
            ifr[jj] = __expf(-(float)dcol * (9.210340371976184f / 64.0f));
        }
        #pragma unroll
        for (int i = 0; i < 4; i++) {
            #pragma unroll
            for (int half = 0; half < 2; half++) {
                const int row = m0 + wm + i*16 + er + half*8;   // global m = b*SS+s
                const int b = row >> 11, s = row & (SS - 1);
                const int ps = pos[row];
                #pragma unroll
                for (int jj = 0; jj < 4; jj++) {
                    const int col = n0 + wn + jj*8 + ec;
                    float e = acc[i][jj][half*2], o = acc[i][jj][half*2+1];
                    float sn, cs;
                    sincosf((float)ps * ifr[jj], &sn, &cs);
                    float e2 = e * cs - o * sn;
                    o        = e * sn + o * cs;
                    e = e2;
                    float eh = __bfloat162float(__float2bfloat16_rn(e));
                    float oh = __bfloat162float(__float2bfloat16_rn(o));
                    const int h = col >> 6, d = col & 63;
                    size_t di = ((size_t)((b << 4) + h) * SS + s) * HD + d;
                    *(uint32_t*)(hiA + di) = pack_bf16(eh, oh);
                    *(uint32_t*)(loA + di) = pack_bf16(e - eh, o - oh);
                }
            }
        }
    }
}

// ---------------------------------------------------------------------------
// Attention fragment loaders
// ---------------------------------------------------------------------------
__device__ __forceinline__ void attn_ldK(uint32_t sKh, uint32_t sKl,
                                         int b_row, int b_ku, int st,
                                         uint32_t kh[4][4], uint32_t kl[4][4])
{
    const int cu = st * 2;
    #pragma unroll
    for (int jn = 0; jn < 4; jn++) {
        uint32_t off = SWZ((uint32_t)((jn*16 + b_row) * 128 + (cu + b_ku) * 16));
        ldsm4(sKh + off, kh[jn]);
        ldsm4(sKl + off, kl[jn]);
    }
}
__device__ __forceinline__ void attn_ldV(uint32_t sVh, uint32_t sVl,
                                         int v_row, int v_cb, int kk,
                                         uint32_t vh[4][4], uint32_t vl[4][4])
{
    #pragma unroll
    for (int jv = 0; jv < 4; jv++) {
        uint32_t off = SWZ((uint32_t)((kk*16 + v_row) * 128 + jv*32 + v_cb));
        ldsm4t(sVh + off, vh[jv]);
        ldsm4t(sVl + off, vl[jv]);
    }
}

// ---------------------------------------------------------------------------
// HMMA flash attention v3: 64 query rows per CTA, 4 warps (16 rows each),
// key tiles of 64.  2 CTAs/SM (112KB smem each) so softmax of one CTA
// overlaps MMAs of the other.  S = split-bf16 (3 MMAs); PV = fp16 P (single)
// x fp16 V hi/lo (2 MMAs).
// ---------------------------------------------------------------------------
#define AQ_TILE 8192
#define AKV_TILE 8192
#define AKV_STAGE (4*AKV_TILE)
#define AKV_NST 3
#define ASMEM (2*AQ_TILE + AKV_NST*AKV_STAGE)   // 112KB

__global__ void __launch_bounds__(128, 2) attn_hmma()
{
    extern __shared__ char smem[];
    const uint32_t sbase = smem_u32(smem);
    const int tid = threadIdx.x, lane = tid & 31, wid = tid >> 5;   // wid 0..3
    const int qt = (int)gridDim.x - 1 - (int)blockIdx.x;            // long first
    const int bh = blockIdx.y;
    const int s0 = qt * 64;
    const int nkt = qt + 1;

    const size_t bhoff = (size_t)bh * SS * HD;
    const __nv_bfloat16* Qh = g_qhi + bhoff + (size_t)s0 * HD;
    const __nv_bfloat16* Ql = g_qlo + bhoff + (size_t)s0 * HD;
    const __nv_bfloat16* kvsrc[4] = {
        g_khi + bhoff, g_klo + bhoff,
        reinterpret_cast<const __nv_bfloat16*>(g_vhi) + bhoff,
        reinterpret_cast<const __nv_bfloat16*>(g_vlo) + bhoff };

    const uint32_t sQ  = sbase;
    const uint32_t sKV = sbase + 2*AQ_TILE;

    {   // Q hi/lo: 64 rows x 8 16B-units each
        #pragma unroll
        for (int j = 0; j < 4; j++) {
            int idx = j * 128 + tid;
            int row = idx >> 3, cu = idx & 7;
            uint32_t off = SWZ((uint32_t)(row * 128 + cu * 16));
            cp16(sQ + off,           Qh + (size_t)row * HD + cu * 8);
            cp16(sQ + AQ_TILE + off, Ql + (size_t)row * HD + cu * 8);
        }
        cp_commit();
    }
    auto fill_kv = [&](int st, int kb) {
        uint32_t sb = sKV + st * AKV_STAGE;
        #pragma unroll
        for (int t = 0; t < 4; t++) {
            const __nv_bfloat16* s = kvsrc[t] + (size_t)kb * 64 * HD;
            #pragma unroll
            for (int r = 0; r < 4; r++) {
                int idx = r * 128 + tid;
                int row = idx >> 3, cu = idx & 7;
                cp16(sb + t * AKV_TILE + SWZ((uint32_t)(row * 128 + cu * 16)),
                     s + (size_t)row * HD + cu * 8);
            }
        }
        cp_commit();
    };
    fill_kv(0, 0);
    if (nkt > 1) fill_kv(1, 1); else cp_commit();   // keep group count consistent

    cp_wait<2>();
    __syncthreads();
    uint32_t qh[4][4], ql[4][4];
    {
        const int a_row = lane & 15, a_ku = lane >> 4;
        #pragma unroll
        for (int st = 0; st < 4; st++) {
            uint32_t off = SWZ((uint32_t)((wid*16 + a_row) * 128 + (st*2 + a_ku) * 16));
            ldsm4(sQ + off, qh[st]);
            ldsm4(sQ + AQ_TILE + off, ql[st]);
        }
    }

    float o_acc[8][4];
    #pragma unroll
    for (int jj = 0; jj < 8; jj++)
        #pragma unroll
        for (int c = 0; c < 4; c++) o_acc[jj][c] = 0.0f;
    float row_max[2] = {-1e30f, -1e30f}, row_l[2] = {0.0f, 0.0f};

    const int b_row = ((lane >> 4) << 3) + (lane & 7);
    const int b_ku  = (lane >> 3) & 1;
    const int v_row = lane & 15;
    const int v_cb  = ((lane >> 4) << 3) * 2;
    const float scale = 0.125f;

    int stg = 0;
    #pragma unroll 1
    for (int kb = 0; kb < nkt; kb++) {
        if (kb == nkt - 1) cp_wait<0>(); else cp_wait<1>();
        __syncthreads();

        if (kb + 2 < nkt) {
            int fs = stg + 2; if (fs >= AKV_NST) fs -= AKV_NST;
            fill_kv(fs, kb + 2);
        }

        const uint32_t sb = sKV + stg * AKV_STAGE;
        const uint32_t sKh = sb, sKl = sb + AKV_TILE;
        const uint32_t sVh = sb + 2*AKV_TILE, sVl = sb + 3*AKV_TILE;

        // ---- S = Q K^T (split-bf16, 3 MMAs) ----
        float sacc[8][4];
        #pragma unroll
        for (int jj = 0; jj < 8; jj++)
            #pragma unroll
            for (int c = 0; c < 4; c++) sacc[jj][c] = 0.0f;

        uint32_t kh[2][4][4], kl[2][4][4];
        attn_ldK(sKh, sKl, b_row, b_ku, 0, kh[0], kl[0]);
        #pragma unroll
        for (int st = 0; st < 4; st++) {
            const int cur = st & 1, nxt = cur ^ 1;
            if (st < 3)
                attn_ldK(sKh, sKl, b_row, b_ku, st + 1, kh[nxt], kl[nxt]);
            #pragma unroll
            for (int jj = 0; jj < 8; jj++) {
                const int j16 = jj >> 1, h = (jj & 1) * 2;
                mma16816(sacc[jj], qh[st], kh[cur][j16][h], kh[cur][j16][h+1]);
                mma16816(sacc[jj], qh[st], kl[cur][j16][h], kl[cur][j16][h+1]);
                mma16816(sacc[jj], ql[st], kh[cur][j16][h], kh[cur][j16][h+1]);
            }
        }

        // ---- prefetch V fragments for kk=0 (overlaps softmax ALU) ----
        uint32_t vh[2][4][4], vl[2][4][4];
        attn_ldV(sVh, sVl, v_row, v_cb, 0, vh[0], vl[0]);

        // ---- online softmax ----
        const bool tmask = (kb == qt);
        #pragma unroll
        for (int rh = 0; rh < 2; rh++) {
            const int grow = s0 + wid*16 + (lane >> 2) + rh*8;
            float mx = -1e30f;
            #pragma unroll
            for (int jj = 0; jj < 8; jj++)
                #pragma unroll
                for (int dc = 0; dc < 2; dc++) {
                    float v = sacc[jj][rh*2+dc] * scale;
                    if (tmask && (kb*64 + jj*8 + 2*(lane&3) + dc > grow)) v = -1e30f;
                    sacc[jj][rh*2+dc] = v;
                    mx = fmaxf(mx, v);
                }
            mx = fmaxf(mx, __shfl_xor_sync(0xffffffffu, mx, 1));
            mx = fmaxf(mx, __shfl_xor_sync(0xffffffffu, mx, 2));
            float mnew = fmaxf(row_max[rh], mx);
            float corr = __expf(row_max[rh] - mnew);
            row_max[rh] = mnew;
            float sum = 0.0f;
            #pragma unroll
            for (int jj = 0; jj < 8; jj++)
                #pragma unroll
                for (int dc = 0; dc < 2; dc++) {
                    float pv = __expf(sacc[jj][rh*2+dc] - mnew);
                    sacc[jj][rh*2+dc] = pv;
                    sum += pv;
                }
            sum += __shfl_xor_sync(0xffffffffu, sum, 1);
            sum += __shfl_xor_sync(0xffffffffu, sum, 2);
            row_l[rh] = row_l[rh] * corr + sum;
            #pragma unroll
            for (int jj = 0; jj < 8; jj++) {
                o_acc[jj][rh*2]   *= corr;
                o_acc[jj][rh*2+1] *= corr;
            }
        }

        // ---- O += P V  (P fp16 single, V fp16 hi/lo: 2 MMAs) ----
        #pragma unroll
        for (int kk = 0; kk < 4; kk++) {
            const int cur = kk & 1, nxt = cur ^ 1;
            if (kk < 3)
                attn_ldV(sVh, sVl, v_row, v_cb, kk + 1, vh[nxt], vl[nxt]);
            uint32_t ph[4];
            #pragma unroll
            for (int u = 0; u < 4; u++) {
                const int jj = 2*kk + (u >> 1), cb = (u & 1) * 2;
                ph[u] = pack_f16(sacc[jj][cb], sacc[jj][cb+1]);
            }
            #pragma unroll
            for (int jj = 0; jj < 8; jj++) {
                const int j16 = jj >> 1, h = (jj & 1) * 2;
                mma16816h(o_acc[jj], ph, vh[cur][j16][h], vh[cur][j16][h+1]);
                mma16816h(o_acc[jj], ph, vl[cur][j16][h], vl[cur][j16][h+1]);
            }
        }
        if (++stg == AKV_NST) stg = 0;
    }

    const int b = bh >> 4, h = bh & 15;
    const float inv0 = 1.0f / row_l[0], inv1 = 1.0f / row_l[1];
    #pragma unroll
    for (int jj = 0; jj < 8; jj++) {
        #pragma unroll
        for (int rh = 0; rh < 2; rh++) {
            const int row = s0 + wid*16 + (lane >> 2) + rh*8;
            const int d   = jj*8 + 2*(lane & 3);
            const float inv = rh ? inv1 : inv0;
            float x = o_acc[jj][rh*2] * inv, y = o_acc[jj][rh*2+1] * inv;
            float hx = __bfloat162float(__float2bfloat16_rn(x));
            float hy = __bfloat162float(__float2bfloat16_rn(y));
            size_t di = ((size_t)(b * SS + row)) * DM + h * HD + d;
            *(uint32_t*)(g_xhi + di) = pack_bf16(hx, hy);
            *(uint32_t*)(g_xlo + di) = pack_bf16(x - hx, y - hy);
        }
    }
}

// ---------------------------------------------------------------------------
extern "C" void kernel_launch(void* const* d_in, const int* in_sizes, int n_in,
                              void* d_out, int out_size)
{
    const float* x  = (const float*)d_in[0];
    const int*  pos = (const int*)  d_in[1];
    const float* wq = (const float*)d_in[2];
    const float* wk = (const float*)d_in[3];
    const float* wv = (const float*)d_in[4];
    const float* wo = (const float*)d_in[5];
    float* out = (float*)d_out;

    void* p;
    cudaGetSymbolAddress(&p, g_xhi);   __nv_bfloat16* xhi = (__nv_bfloat16*)p;
    cudaGetSymbolAddress(&p, g_xlo);   __nv_bfloat16* xlo = (__nv_bfloat16*)p;
    cudaGetSymbolAddress(&p, g_whi);   __nv_bfloat16* whi = (__nv_bfloat16*)p;
    cudaGetSymbolAddress(&p, g_wlo);   __nv_bfloat16* wlo = (__nv_bfloat16*)p;

    cudaFuncSetAttribute(gemm_hmma<true>,  cudaFuncAttributeMaxDynamicSharedMemorySize, GK_SMEM);
    cudaFuncSetAttribute(gemm_hmma<false>, cudaFuncAttributeMaxDynamicSharedMemorySize, GK_SMEM);
    cudaFuncSetAttribute(attn_hmma, cudaFuncAttributeMaxDynamicSharedMemorySize, ASMEM);

    // 0) split-convert x and weights to bf16 hi/lo
    conv_hilo<<<(BSD/4 + 255)/256, 256>>>((const float4*)x, xhi, xlo, BSD/4);
    conv_w<<<dim3(DM*DM/4/256, 4), 256>>>((const float4*)wq, (const float4*)wk,
                                          (const float4*)wv, (const float4*)wo);

    // 1) q,k,v = x @ {wq,wk,wv}^T with fused RoPE + head split
    //    -> q,k bf16 hi/lo, v fp16 hi/lo
    gemm_hmma<true><<<dim3(DM/128, MT/128, 3), 256, GK_SMEM>>>(xhi, xlo, whi, wlo, pos, nullptr);

    // 2) HMMA flash attention (64-row CTAs, 2/SM) -> g_xhi/g_xlo (bf16 hi/lo)
    attn_hmma<<<dim3(SS/64, BB*NH), 128, ASMEM>>>();

    // 3) out = attn @ wo^T
    gemm_hmma<false><<<dim3(DM/128, MT/128, 1), 256, GK_SMEM>>>(
        xhi, xlo, whi + 3*(size_t)DM*DM, wlo + 3*(size_t)DM*DM, nullptr, out);
}

// round 12
// speedup vs baseline: 1.3207x; 1.2069x over previous
#include <cuda_runtime.h>
#include <cuda_bf16.h>
#include <cuda_fp16.h>
#include <math.h>
#include <stdint.h>

#define BB 4
#define SS 2048
#define DM 1024
#define NH 16
#define HD 64
#define MT (BB*SS)          // 8192 rows
#define BSD (MT*DM)         // 8,388,608 elements per matrix

// Scratch (static device globals)
static __device__ __align__(16) __half        g_xhi[BSD];   // x / attn-out, fp16 hi
static __device__ __align__(16) __half        g_xlo[BSD];   // fp16 lo
static __device__ __align__(16) __half        g_w[4*DM*DM]; // weights, single fp16
static __device__ __align__(16) __nv_bfloat16 g_qhi[BSD], g_qlo[BSD];
static __device__ __align__(16) __nv_bfloat16 g_khi[BSD], g_klo[BSD];
static __device__ __align__(16) __half        g_vhi[BSD], g_vlo[BSD];   // V fp16 hi/lo

// ---------------------------------------------------------------------------
// PTX helpers (compute_103 baseline: mma.sync / ldmatrix / cp.async)
// ---------------------------------------------------------------------------
__device__ __forceinline__ uint32_t smem_u32(const void* p) {
    uint32_t a;
    asm("{ .reg .u64 t; cvta.to.shared.u64 t, %1; cvt.u32.u64 %0, t; }" : "=r"(a) : "l"(p));
    return a;
}
__device__ __forceinline__ void cp16(uint32_t saddr, const void* g) {
    asm volatile("cp.async.cg.shared.global [%0], [%1], 16;" :: "r"(saddr), "l"(g) : "memory");
}
__device__ __forceinline__ void cp_commit() {
    asm volatile("cp.async.commit_group;" ::: "memory");
}
template <int N>
__device__ __forceinline__ void cp_wait() {
    asm volatile("cp.async.wait_group %0;" :: "n"(N) : "memory");
}
__device__ __forceinline__ void ldsm4(uint32_t addr, uint32_t r[4]) {
    asm volatile("ldmatrix.sync.aligned.m8n8.x4.shared.b16 {%0,%1,%2,%3}, [%4];"
                 : "=r"(r[0]), "=r"(r[1]), "=r"(r[2]), "=r"(r[3]) : "r"(addr));
}
__device__ __forceinline__ void ldsm4t(uint32_t addr, uint32_t r[4]) {
    asm volatile("ldmatrix.sync.aligned.m8n8.x4.trans.shared.b16 {%0,%1,%2,%3}, [%4];"
                 : "=r"(r[0]), "=r"(r[1]), "=r"(r[2]), "=r"(r[3]) : "r"(addr));
}
__device__ __forceinline__ void mma16816(float c[4], const uint32_t a[4],
                                         uint32_t b0, uint32_t b1) {
    asm volatile(
        "mma.sync.aligned.m16n8k16.row.col.f32.bf16.bf16.f32 "
        "{%0,%1,%2,%3}, {%4,%5,%6,%7}, {%8,%9}, {%0,%1,%2,%3};"
        : "+f"(c[0]), "+f"(c[1]), "+f"(c[2]), "+f"(c[3])
        : "r"(a[0]), "r"(a[1]), "r"(a[2]), "r"(a[3]), "r"(b0), "r"(b1));
}
__device__ __forceinline__ void mma16816h(float c[4], const uint32_t a[4],
                                          uint32_t b0, uint32_t b1) {
    asm volatile(
        "mma.sync.aligned.m16n8k16.row.col.f32.f16.f16.f32 "
        "{%0,%1,%2,%3}, {%4,%5,%6,%7}, {%8,%9}, {%0,%1,%2,%3};"
        : "+f"(c[0]), "+f"(c[1]), "+f"(c[2]), "+f"(c[3])
        : "r"(a[0]), "r"(a[1]), "r"(a[2]), "r"(a[3]), "r"(b0), "r"(b1));
}
#define SWZ(off) ((off) ^ (((off) >> 3) & 0x70))

__device__ __forceinline__ uint32_t pack_bf16(float x, float y) {
    __nv_bfloat162 t(__float2bfloat16_rn(x), __float2bfloat16_rn(y));
    return *(uint32_t*)&t;
}
__device__ __forceinline__ uint32_t pack_f16(float x, float y) {
    __half2 t = __floats2half2_rn(x, y);
    return *(uint32_t*)&t;
}

// ---------------------------------------------------------------------------
// fp32 -> fp16 (hi, lo) split conversion for x / attention output.
// ---------------------------------------------------------------------------
__global__ void conv_hilo(const float4* __restrict__ src,
                          __half* __restrict__ hi,
                          __half* __restrict__ lo, int n4)
{
    int i = blockIdx.x * blockDim.x + threadIdx.x;
    if (i >= n4) return;
    float4 v = src[i];
    float f[4] = {v.x, v.y, v.z, v.w};
    uint32_t h2[2], l2[2];
    #pragma unroll
    for (int j = 0; j < 2; j++) {
        float h0 = __half2float(__float2half_rn(f[2*j]));
        float h1 = __half2float(__float2half_rn(f[2*j+1]));
        h2[j] = pack_f16(f[2*j], f[2*j+1]);
        l2[j] = pack_f16(f[2*j] - h0, f[2*j+1] - h1);
    }
    *(uint2*)(hi + 4*(size_t)i) = *(uint2*)h2;
    *(uint2*)(lo + 4*(size_t)i) = *(uint2*)l2;
}

// All 4 weight matrices -> single fp16 (blockIdx.y selects the matrix).
__global__ void conv_w(const float4* __restrict__ w0, const float4* __restrict__ w1,
                       const float4* __restrict__ w2, const float4* __restrict__ w3)
{
    const int z = blockIdx.y;
    const float4* src = (z == 0) ? w0 : (z == 1) ? w1 : (z == 2) ? w2 : w3;
    int i = blockIdx.x * blockDim.x + threadIdx.x;          // < DM*DM/4
    float4 v = src[i];
    uint32_t h2[2] = { pack_f16(v.x, v.y), pack_f16(v.z, v.w) };
    *(uint2*)(g_w + (size_t)z * DM * DM + 4*(size_t)i) = *(uint2*)h2;
}

// ---------------------------------------------------------------------------
// GEMM fragment loader: A hi/lo (64 rows) + B single (32 cols), one k16 step.
// ---------------------------------------------------------------------------
__device__ __forceinline__ void gemm_ldfrag(
    uint32_t sAh, uint32_t sAl, uint32_t sB,
    int wm, int wn, int a_row, int a_ku, int b_row, int b_ku, int q,
    uint32_t ah[4][4], uint32_t al[4][4], uint32_t b[2][4])
{
    const int cu = q * 2;
    #pragma unroll
    for (int i = 0; i < 4; i++) {
        uint32_t off = SWZ((uint32_t)((wm + i*16 + a_row) * 128 + (cu + a_ku) * 16));
        ldsm4(sAh + off, ah[i]);
        ldsm4(sAl + off, al[i]);
    }
    #pragma unroll
    for (int j = 0; j < 2; j++) {
        uint32_t off = SWZ((uint32_t)((wn + j*16 + b_row) * 128 + (cu + b_ku) * 16));
        ldsm4(sB + off, b[j]);
    }
}

// ---------------------------------------------------------------------------
// HMMA fp16 2-term GEMM: C[m][n] = sum_k (Ahi+Alo)[m][k] * W[n][k]
// 128x128 CTA tile, 256 threads (8 warps), warp tile 64x32, K-chunk 64.
// 3-stage cp.async pipeline (144KB smem: Ahi, Alo, W per stage).
// ROPE=true: fused RoPE + head-split epilogue (Q/K bf16 hi/lo, V fp16 hi/lo).
// ---------------------------------------------------------------------------
#define GK_TILE   16384                 // 128 rows x 128B (64 fp16)
#define GK_STAGE  (3*GK_TILE)           // Ahi, Alo, W = 48KB
#define GK_NST    3
#define GK_SMEM   (GK_NST*GK_STAGE)     // 144KB
#define NKCH      16

template<bool ROPE>
__global__ void __launch_bounds__(256, 1) gemm_hmma(
    const __half* __restrict__ Ahi, const __half* __restrict__ Alo,
    const __half* __restrict__ W,
    const int* __restrict__ pos, float* __restrict__ C)
{
    extern __shared__ char smem[];
    const uint32_t sbase = smem_u32(smem);
    const int tid = threadIdx.x, lane = tid & 31, wid = tid >> 5;
    const int n0 = blockIdx.x * 128, m0 = blockIdx.y * 128, z = blockIdx.z;

    const __half* __restrict__ srcs[3] = {
        Ahi + (size_t)m0 * DM,
        Alo + (size_t)m0 * DM,
        W + (size_t)z * DM * DM + (size_t)n0 * DM };

    auto fill = [&](int st, int kt) {
        uint32_t sb = sbase + st * GK_STAGE;
        #pragma unroll
        for (int t = 0; t < 3; t++) {
            const __half* s = srcs[t] + kt * 64;
            #pragma unroll
            for (int j = 0; j < 4; j++) {
                int idx = j * 256 + tid;
                int row = idx >> 3, cu = idx & 7;
                cp16(sb + t * GK_TILE + SWZ((uint32_t)(row * 128 + cu * 16)),
                     s + (size_t)row * DM + cu * 8);
            }
        }
        cp_commit();
    };

    const int wm = (wid & 1) * 64;
    const int wn = (wid >> 1) * 32;
    const int a_row = lane & 15;
    const int a_ku  = lane >> 4;
    const int b_row = ((lane >> 4) << 3) + (lane & 7);
    const int b_ku  = (lane >> 3) & 1;

    float acc[4][4][4];
    #pragma unroll
    for (int i = 0; i < 4; i++)
        #pragma unroll
        for (int j = 0; j < 4; j++)
            #pragma unroll
            for (int c = 0; c < 4; c++) acc[i][j][c] = 0.0f;

    fill(0, 0);
    fill(1, 1);

    uint32_t ah[2][4][4], al[2][4][4], bf[2][2][4];

    int st = 0;
    #pragma unroll 1
    for (int kt = 0; kt < NKCH; kt++) {
        if (kt == NKCH - 1) cp_wait<0>(); else cp_wait<1>();
        __syncthreads();

        if (kt + 2 < NKCH) {
            int fs = st + 2; if (fs >= GK_NST) fs -= GK_NST;
            fill(fs, kt + 2);
        }

        const uint32_t sb  = sbase + st * GK_STAGE;
        const uint32_t sAh = sb, sAl = sb + GK_TILE, sB = sb + 2*GK_TILE;

        gemm_ldfrag(sAh, sAl, sB, wm, wn, a_row, a_ku, b_row, b_ku, 0,
                    ah[0], al[0], bf[0]);

        #pragma unroll
        for (int q = 0; q < 4; q++) {
            const int cur = q & 1, nxt = cur ^ 1;
            if (q < 3)
                gemm_ldfrag(sAh, sAl, sB, wm, wn, a_row, a_ku, b_row, b_ku, q + 1,
                            ah[nxt], al[nxt], bf[nxt]);
            #pragma unroll
            for (int i = 0; i < 4; i++)
                #pragma unroll
                for (int jj = 0; jj < 4; jj++) {
                    const int j16 = jj >> 1, h = (jj & 1) * 2;
                    mma16816h(acc[i][jj], ah[cur][i], bf[cur][j16][h], bf[cur][j16][h+1]);
                    mma16816h(acc[i][jj], al[cur][i], bf[cur][j16][h], bf[cur][j16][h+1]);
                }
        }
        if (++st == GK_NST) st = 0;
    }

    const int er = lane >> 2;
    const int ec = (lane & 3) * 2;

    if constexpr (!ROPE) {
        #pragma unroll
        for (int i = 0; i < 4; i++)
            #pragma unroll
            for (int jj = 0; jj < 4; jj++) {
                const int row = m0 + wm + i*16 + er;
                const int col = n0 + wn + jj*8 + ec;
                *(float2*)(C + (size_t)row * DM + col)       = make_float2(acc[i][jj][0], acc[i][jj][1]);
                *(float2*)(C + (size_t)(row + 8) * DM + col) = make_float2(acc[i][jj][2], acc[i][jj][3]);
            }
    } else if (z == 2) {
        // V: no RoPE; head split + fp16 hi/lo
        #pragma unroll
        for (int i = 0; i < 4; i++) {
            #pragma unroll
            for (int half = 0; half < 2; half++) {
                const int row = m0 + wm + i*16 + er + half*8;   // global m = b*SS+s
                const int b = row >> 11, s = row & (SS - 1);
                #pragma unroll
                for (int jj = 0; jj < 4; jj++) {
                    const int col = n0 + wn + jj*8 + ec;
                    float e = acc[i][jj][half*2], o = acc[i][jj][half*2+1];
                    float eh = __half2float(__float2half_rn(e));
                    float oh = __half2float(__float2half_rn(o));
                    const int h = col >> 6, d = col & 63;
                    size_t di = ((size_t)((b << 4) + h) * SS + s) * HD + d;
                    *(uint32_t*)(g_vhi + di) = pack_f16(e, o);
                    *(uint32_t*)(g_vlo + di) = pack_f16(e - eh, o - oh);
                }
            }
        }
    } else {
        // Q/K: fused RoPE + head split + bf16 hi/lo
        __nv_bfloat16* hiA = (z == 0) ? g_qhi : g_khi;
        __nv_bfloat16* loA = (z == 0) ? g_qlo : g_klo;
        float ifr[4];
        #pragma unroll
        for (int jj = 0; jj < 4; jj++) {
            int dcol = (wn & 32) + jj*8 + ec;        // even d index within head
            ifr[jj] = __expf(-(float)dcol * (9.210340371976184f / 64.0f));
        }
        #pragma unroll
        for (int i = 0; i < 4; i++) {
            #pragma unroll
            for (int half = 0; half < 2; half++) {
                const int row = m0 + wm + i*16 + er + half*8;   // global m = b*SS+s
                const int b = row >> 11, s = row & (SS - 1);
                const int ps = pos[row];
                #pragma unroll
                for (int jj = 0; jj < 4; jj++) {
                    const int col = n0 + wn + jj*8 + ec;
                    float e = acc[i][jj][half*2], o = acc[i][jj][half*2+1];
                    float sn, cs;
                    sincosf((float)ps * ifr[jj], &sn, &cs);
                    float e2 = e * cs - o * sn;
                    o        = e * sn + o * cs;
                    e = e2;
                    float eh = __bfloat162float(__float2bfloat16_rn(e));
                    float oh = __bfloat162float(__float2bfloat16_rn(o));
                    const int h = col >> 6, d = col & 63;
                    size_t di = ((size_t)((b << 4) + h) * SS + s) * HD + d;
                    *(uint32_t*)(hiA + di) = pack_bf16(eh, oh);
                    *(uint32_t*)(loA + di) = pack_bf16(e - eh, o - oh);
                }
            }
        }
    }
}

// ---------------------------------------------------------------------------
// Attention fragment loaders
// ---------------------------------------------------------------------------
__device__ __forceinline__ void attn_ldK(uint32_t sKh, uint32_t sKl,
                                         int b_row, int b_ku, int st,
                                         uint32_t kh[4][4], uint32_t kl[4][4])
{
    const int cu = st * 2;
    #pragma unroll
    for (int jn = 0; jn < 4; jn++) {
        uint32_t off = SWZ((uint32_t)((jn*16 + b_row) * 128 + (cu + b_ku) * 16));
        ldsm4(sKh + off, kh[jn]);
        ldsm4(sKl + off, kl[jn]);
    }
}
__device__ __forceinline__ void attn_ldV(uint32_t sVh, uint32_t sVl,
                                         int v_row, int v_cb, int kk,
                                         uint32_t vh[4][4], uint32_t vl[4][4])
{
    #pragma unroll
    for (int jv = 0; jv < 4; jv++) {
        uint32_t off = SWZ((uint32_t)((kk*16 + v_row) * 128 + jv*32 + v_cb));
        ldsm4t(sVh + off, vh[jv]);
        ldsm4t(sVl + off, vl[jv]);
    }
}

// ---------------------------------------------------------------------------
// HMMA flash attention (round-11 proven version): 64 query rows per CTA,
// 4 warps, 2 CTAs/SM.  S = split-bf16 (3 MMAs); PV = fp16 P x fp16 V hi/lo (2).
// Output now written as fp16 hi/lo for the 2-term WO GEMM.
// ---------------------------------------------------------------------------
#define AQ_TILE 8192
#define AKV_TILE 8192
#define AKV_STAGE (4*AKV_TILE)
#define AKV_NST 3
#define ASMEM (2*AQ_TILE + AKV_NST*AKV_STAGE)   // 112KB

__global__ void __launch_bounds__(128, 2) attn_hmma()
{
    extern __shared__ char smem[];
    const uint32_t sbase = smem_u32(smem);
    const int tid = threadIdx.x, lane = tid & 31, wid = tid >> 5;   // wid 0..3
    const int qt = (int)gridDim.x - 1 - (int)blockIdx.x;            // long first
    const int bh = blockIdx.y;
    const int s0 = qt * 64;
    const int nkt = qt + 1;

    const size_t bhoff = (size_t)bh * SS * HD;
    const __nv_bfloat16* Qh = g_qhi + bhoff + (size_t)s0 * HD;
    const __nv_bfloat16* Ql = g_qlo + bhoff + (size_t)s0 * HD;
    const __nv_bfloat16* kvsrc[4] = {
        g_khi + bhoff, g_klo + bhoff,
        reinterpret_cast<const __nv_bfloat16*>(g_vhi) + bhoff,
        reinterpret_cast<const __nv_bfloat16*>(g_vlo) + bhoff };

    const uint32_t sQ  = sbase;
    const uint32_t sKV = sbase + 2*AQ_TILE;

    {   // Q hi/lo: 64 rows x 8 16B-units each
        #pragma unroll
        for (int j = 0; j < 4; j++) {
            int idx = j * 128 + tid;
            int row = idx >> 3, cu = idx & 7;
            uint32_t off = SWZ((uint32_t)(row * 128 + cu * 16));
            cp16(sQ + off,           Qh + (size_t)row * HD + cu * 8);
            cp16(sQ + AQ_TILE + off, Ql + (size_t)row * HD + cu * 8);
        }
        cp_commit();
    }
    auto fill_kv = [&](int st, int kb) {
        uint32_t sb = sKV + st * AKV_STAGE;
        #pragma unroll
        for (int t = 0; t < 4; t++) {
            const __nv_bfloat16* s = kvsrc[t] + (size_t)kb * 64 * HD;
            #pragma unroll
            for (int r = 0; r < 4; r++) {
                int idx = r * 128 + tid;
                int row = idx >> 3, cu = idx & 7;
                cp16(sb + t * AKV_TILE + SWZ((uint32_t)(row * 128 + cu * 16)),
                     s + (size_t)row * HD + cu * 8);
            }
        }
        cp_commit();
    };
    fill_kv(0, 0);
    if (nkt > 1) fill_kv(1, 1); else cp_commit();   // keep group count consistent

    cp_wait<2>();
    __syncthreads();
    uint32_t qh[4][4], ql[4][4];
    {
        const int a_row = lane & 15, a_ku = lane >> 4;
        #pragma unroll
        for (int st = 0; st < 4; st++) {
            uint32_t off = SWZ((uint32_t)((wid*16 + a_row) * 128 + (st*2 + a_ku) * 16));
            ldsm4(sQ + off, qh[st]);
            ldsm4(sQ + AQ_TILE + off, ql[st]);
        }
    }

    float o_acc[8][4];
    #pragma unroll
    for (int jj = 0; jj < 8; jj++)
        #pragma unroll
        for (int c = 0; c < 4; c++) o_acc[jj][c] = 0.0f;
    float row_max[2] = {-1e30f, -1e30f}, row_l[2] = {0.0f, 0.0f};

    const int b_row = ((lane >> 4) << 3) + (lane & 7);
    const int b_ku  = (lane >> 3) & 1;
    const int v_row = lane & 15;
    const int v_cb  = ((lane >> 4) << 3) * 2;
    const float scale = 0.125f;

    int stg = 0;
    #pragma unroll 1
    for (int kb = 0; kb < nkt; kb++) {
        if (kb == nkt - 1) cp_wait<0>(); else cp_wait<1>();
        __syncthreads();

        if (kb + 2 < nkt) {
            int fs = stg + 2; if (fs >= AKV_NST) fs -= AKV_NST;
            fill_kv(fs, kb + 2);
        }

        const uint32_t sb = sKV + stg * AKV_STAGE;
        const uint32_t sKh = sb, sKl = sb + AKV_TILE;
        const uint32_t sVh = sb + 2*AKV_TILE, sVl = sb + 3*AKV_TILE;

        // ---- S = Q K^T (split-bf16, 3 MMAs) ----
        float sacc[8][4];
        #pragma unroll
        for (int jj = 0; jj < 8; jj++)
            #pragma unroll
            for (int c = 0; c < 4; c++) sacc[jj][c] = 0.0f;

        uint32_t kh[2][4][4], kl[2][4][4];
        attn_ldK(sKh, sKl, b_row, b_ku, 0, kh[0], kl[0]);
        #pragma unroll
        for (int st = 0; st < 4; st++) {
            const int cur = st & 1, nxt = cur ^ 1;
            if (st < 3)
                attn_ldK(sKh, sKl, b_row, b_ku, st + 1, kh[nxt], kl[nxt]);
            #pragma unroll
            for (int jj = 0; jj < 8; jj++) {
                const int j16 = jj >> 1, h = (jj & 1) * 2;
                mma16816(sacc[jj], qh[st], kh[cur][j16][h], kh[cur][j16][h+1]);
                mma16816(sacc[jj], qh[st], kl[cur][j16][h], kl[cur][j16][h+1]);
                mma16816(sacc[jj], ql[st], kh[cur][j16][h], kh[cur][j16][h+1]);
            }
        }

        // ---- prefetch V fragments for kk=0 (overlaps softmax ALU) ----
        uint32_t vh[2][4][4], vl[2][4][4];
        attn_ldV(sVh, sVl, v_row, v_cb, 0, vh[0], vl[0]);

        // ---- online softmax ----
        const bool tmask = (kb == qt);
        #pragma unroll
        for (int rh = 0; rh < 2; rh++) {
            const int grow = s0 + wid*16 + (lane >> 2) + rh*8;
            float mx = -1e30f;
            #pragma unroll
            for (int jj = 0; jj < 8; jj++)
                #pragma unroll
                for (int dc = 0; dc < 2; dc++) {
                    float v = sacc[jj][rh*2+dc] * scale;
                    if (tmask && (kb*64 + jj*8 + 2*(lane&3) + dc > grow)) v = -1e30f;
                    sacc[jj][rh*2+dc] = v;
                    mx = fmaxf(mx, v);
                }
            mx = fmaxf(mx, __shfl_xor_sync(0xffffffffu, mx, 1));
            mx = fmaxf(mx, __shfl_xor_sync(0xffffffffu, mx, 2));
            float mnew = fmaxf(row_max[rh], mx);
            float corr = __expf(row_max[rh] - mnew);
            row_max[rh] = mnew;
            float sum = 0.0f;
            #pragma unroll
            for (int jj = 0; jj < 8; jj++)
                #pragma unroll
                for (int dc = 0; dc < 2; dc++) {
                    float pv = __expf(sacc[jj][rh*2+dc] - mnew);
                    sacc[jj][rh*2+dc] = pv;
                    sum += pv;
                }
            sum += __shfl_xor_sync(0xffffffffu, sum, 1);
            sum += __shfl_xor_sync(0xffffffffu, sum, 2);
            row_l[rh] = row_l[rh] * corr + sum;
            #pragma unroll
            for (int jj = 0; jj < 8; jj++) {
                o_acc[jj][rh*2]   *= corr;
                o_acc[jj][rh*2+1] *= corr;
            }
        }

        // ---- O += P V  (P fp16 single, V fp16 hi/lo: 2 MMAs) ----
        #pragma unroll
        for (int kk = 0; kk < 4; kk++) {
            const int cur = kk & 1, nxt = cur ^ 1;
            if (kk < 3)
                attn_ldV(sVh, sVl, v_row, v_cb, kk + 1, vh[nxt], vl[nxt]);
            uint32_t ph[4];
            #pragma unroll
            for (int u = 0; u < 4; u++) {
                const int jj = 2*kk + (u >> 1), cb = (u & 1) * 2;
                ph[u] = pack_f16(sacc[jj][cb], sacc[jj][cb+1]);
            }
            #pragma unroll
            for (int jj = 0; jj < 8; jj++) {
                const int j16 = jj >> 1, h = (jj & 1) * 2;
                mma16816h(o_acc[jj], ph, vh[cur][j16][h], vh[cur][j16][h+1]);
                mma16816h(o_acc[jj], ph, vl[cur][j16][h], vl[cur][j16][h+1]);
            }
        }
        if (++stg == AKV_NST) stg = 0;
    }

    const int b = bh >> 4, h = bh & 15;
    const float inv0 = 1.0f / row_l[0], inv1 = 1.0f / row_l[1];
    #pragma unroll
    for (int jj = 0; jj < 8; jj++) {
        #pragma unroll
        for (int rh = 0; rh < 2; rh++) {
            const int row = s0 + wid*16 + (lane >> 2) + rh*8;
            const int d   = jj*8 + 2*(lane & 3);
            const float inv = rh ? inv1 : inv0;
            float x = o_acc[jj][rh*2] * inv, y = o_acc[jj][rh*2+1] * inv;
            float hx = __half2float(__float2half_rn(x));
            float hy = __half2float(__float2half_rn(y));
            size_t di = ((size_t)(b * SS + row)) * DM + h * HD + d;
            *(uint32_t*)(g_xhi + di) = pack_f16(x, y);
            *(uint32_t*)(g_xlo + di) = pack_f16(x - hx, y - hy);
        }
    }
}

// ---------------------------------------------------------------------------
extern "C" void kernel_launch(void* const* d_in, const int* in_sizes, int n_in,
                              void* d_out, int out_size)
{
    const float* x  = (const float*)d_in[0];
    const int*  pos = (const int*)  d_in[1];
    const float* wq = (const float*)d_in[2];
    const float* wk = (const float*)d_in[3];
    const float* wv = (const float*)d_in[4];
    const float* wo = (const float*)d_in[5];
    float* out = (float*)d_out;

    void* p;
    cudaGetSymbolAddress(&p, g_xhi);   __half* xhi = (__half*)p;
    cudaGetSymbolAddress(&p, g_xlo);   __half* xlo = (__half*)p;
    cudaGetSymbolAddress(&p, g_w);     __half* w   = (__half*)p;

    cudaFuncSetAttribute(gemm_hmma<true>,  cudaFuncAttributeMaxDynamicSharedMemorySize, GK_SMEM);
    cudaFuncSetAttribute(gemm_hmma<false>, cudaFuncAttributeMaxDynamicSharedMemorySize, GK_SMEM);
    cudaFuncSetAttribute(attn_hmma, cudaFuncAttributeMaxDynamicSharedMemorySize, ASMEM);

    // 0) convert x -> fp16 hi/lo, weights -> single fp16
    conv_hilo<<<(BSD/4 + 255)/256, 256>>>((const float4*)x, xhi, xlo, BSD/4);
    conv_w<<<dim3(DM*DM/4/256, 4), 256>>>((const float4*)wq, (const float4*)wk,
                                          (const float4*)wv, (const float4*)wo);

    // 1) q,k,v = x @ {wq,wk,wv}^T with fused RoPE + head split
    //    -> q,k bf16 hi/lo, v fp16 hi/lo
    gemm_hmma<true><<<dim3(DM/128, MT/128, 3), 256, GK_SMEM>>>(xhi, xlo, w, pos, nullptr);

    // 2) HMMA flash attention (64-row CTAs, 2/SM) -> g_xhi/g_xlo (fp16 hi/lo)
    attn_hmma<<<dim3(SS/64, BB*NH), 128, ASMEM>>>();

    // 3) out = attn @ wo^T
    gemm_hmma<false><<<dim3(DM/128, MT/128, 1), 256, GK_SMEM>>>(
        xhi, xlo, w + 3*(size_t)DM*DM, nullptr, out);
}

// round 13
// speedup vs baseline: 1.3261x; 1.0040x over previous
#include <cuda_runtime.h>
#include <cuda_bf16.h>
#include <cuda_fp16.h>
#include <math.h>
#include <stdint.h>

#define BB 4
#define SS 2048
#define DM 1024
#define NH 16
#define HD 64
#define MT (BB*SS)          // 8192 rows
#define BSD (MT*DM)         // 8,388,608 elements per matrix

// Scratch (static device globals)
static __device__ __align__(16) __half        g_xhi[BSD];   // x / attn-out, fp16 hi
static __device__ __align__(16) __half        g_xlo[BSD];   // fp16 lo
static __device__ __align__(16) __half        g_w[4*DM*DM]; // weights, single fp16
static __device__ __align__(16) __nv_bfloat16 g_qhi[BSD], g_qlo[BSD];
static __device__ __align__(16) __nv_bfloat16 g_khi[BSD], g_klo[BSD];
static __device__ __align__(16) __half        g_vhi[BSD], g_vlo[BSD];   // V fp16 hi/lo

// ---------------------------------------------------------------------------
// PTX helpers (compute_103 baseline: mma.sync / ldmatrix / cp.async)
// ---------------------------------------------------------------------------
__device__ __forceinline__ uint32_t smem_u32(const void* p) {
    uint32_t a;
    asm("{ .reg .u64 t; cvta.to.shared.u64 t, %1; cvt.u32.u64 %0, t; }" : "=r"(a) : "l"(p));
    return a;
}
__device__ __forceinline__ void cp16(uint32_t saddr, const void* g) {
    asm volatile("cp.async.cg.shared.global [%0], [%1], 16;" :: "r"(saddr), "l"(g) : "memory");
}
__device__ __forceinline__ void cp_commit() {
    asm volatile("cp.async.commit_group;" ::: "memory");
}
template <int N>
__device__ __forceinline__ void cp_wait() {
    asm volatile("cp.async.wait_group %0;" :: "n"(N) : "memory");
}
__device__ __forceinline__ void ldsm4(uint32_t addr, uint32_t r[4]) {
    asm volatile("ldmatrix.sync.aligned.m8n8.x4.shared.b16 {%0,%1,%2,%3}, [%4];"
                 : "=r"(r[0]), "=r"(r[1]), "=r"(r[2]), "=r"(r[3]) : "r"(addr));
}
__device__ __forceinline__ void ldsm4t(uint32_t addr, uint32_t r[4]) {
    asm volatile("ldmatrix.sync.aligned.m8n8.x4.trans.shared.b16 {%0,%1,%2,%3}, [%4];"
                 : "=r"(r[0]), "=r"(r[1]), "=r"(r[2]), "=r"(r[3]) : "r"(addr));
}
__device__ __forceinline__ void mma16816(float c[4], const uint32_t a[4],
                                         uint32_t b0, uint32_t b1) {
    asm volatile(
        "mma.sync.aligned.m16n8k16.row.col.f32.bf16.bf16.f32 "
        "{%0,%1,%2,%3}, {%4,%5,%6,%7}, {%8,%9}, {%0,%1,%2,%3};"
        : "+f"(c[0]), "+f"(c[1]), "+f"(c[2]), "+f"(c[3])
        : "r"(a[0]), "r"(a[1]), "r"(a[2]), "r"(a[3]), "r"(b0), "r"(b1));
}
__device__ __forceinline__ void mma16816h(float c[4], const uint32_t a[4],
                                          uint32_t b0, uint32_t b1) {
    asm volatile(
        "mma.sync.aligned.m16n8k16.row.col.f32.f16.f16.f32 "
        "{%0,%1,%2,%3}, {%4,%5,%6,%7}, {%8,%9}, {%0,%1,%2,%3};"
        : "+f"(c[0]), "+f"(c[1]), "+f"(c[2]), "+f"(c[3])
        : "r"(a[0]), "r"(a[1]), "r"(a[2]), "r"(a[3]), "r"(b0), "r"(b1));
}
#define SWZ(off) ((off) ^ (((off) >> 3) & 0x70))

__device__ __forceinline__ uint32_t pack_bf16(float x, float y) {
    __nv_bfloat162 t(__float2bfloat16_rn(x), __float2bfloat16_rn(y));
    return *(uint32_t*)&t;
}
__device__ __forceinline__ uint32_t pack_f16(float x, float y) {
    __half2 t = __floats2half2_rn(x, y);
    return *(uint32_t*)&t;
}

// ---------------------------------------------------------------------------
// fp32 -> fp16 (hi, lo) split conversion for x / attention output.
// ---------------------------------------------------------------------------
__global__ void conv_hilo(const float4* __restrict__ src,
                          __half* __restrict__ hi,
                          __half* __restrict__ lo, int n4)
{
    int i = blockIdx.x * blockDim.x + threadIdx.x;
    if (i >= n4) return;
    float4 v = src[i];
    float f[4] = {v.x, v.y, v.z, v.w};
    uint32_t h2[2], l2[2];
    #pragma unroll
    for (int j = 0; j < 2; j++) {
        float h0 = __half2float(__float2half_rn(f[2*j]));
        float h1 = __half2float(__float2half_rn(f[2*j+1]));
        h2[j] = pack_f16(f[2*j], f[2*j+1]);
        l2[j] = pack_f16(f[2*j] - h0, f[2*j+1] - h1);
    }
    *(uint2*)(hi + 4*(size_t)i) = *(uint2*)h2;
    *(uint2*)(lo + 4*(size_t)i) = *(uint2*)l2;
}

// All 4 weight matrices -> single fp16 (blockIdx.y selects the matrix).
__global__ void conv_w(const float4* __restrict__ w0, const float4* __restrict__ w1,
                       const float4* __restrict__ w2, const float4* __restrict__ w3)
{
    const int z = blockIdx.y;
    const float4* src = (z == 0) ? w0 : (z == 1) ? w1 : (z == 2) ? w2 : w3;
    int i = blockIdx.x * blockDim.x + threadIdx.x;          // < DM*DM/4
    float4 v = src[i];
    uint32_t h2[2] = { pack_f16(v.x, v.y), pack_f16(v.z, v.w) };
    *(uint2*)(g_w + (size_t)z * DM * DM + 4*(size_t)i) = *(uint2*)h2;
}

// ---------------------------------------------------------------------------
// GEMM fragment loader: A hi/lo (64 rows) + B single (32 cols), one k16 step.
// ---------------------------------------------------------------------------
__device__ __forceinline__ void gemm_ldfrag(
    uint32_t sAh, uint32_t sAl, uint32_t sB,
    int wm, int wn, int a_row, int a_ku, int b_row, int b_ku, int q,
    uint32_t ah[4][4], uint32_t al[4][4], uint32_t b[2][4])
{
    const int cu = q * 2;
    #pragma unroll
    for (int i = 0; i < 4; i++) {
        uint32_t off = SWZ((uint32_t)((wm + i*16 + a_row) * 128 + (cu + a_ku) * 16));
        ldsm4(sAh + off, ah[i]);
        ldsm4(sAl + off, al[i]);
    }
    #pragma unroll
    for (int j = 0; j < 2; j++) {
        uint32_t off = SWZ((uint32_t)((wn + j*16 + b_row) * 128 + (cu + b_ku) * 16));
        ldsm4(sB + off, b[j]);
    }
}

// ---------------------------------------------------------------------------
// HMMA fp16 2-term GEMM: C[m][n] = sum_k (Ahi+Alo)[m][k] * W[n][k]
// 128x128 CTA tile, 256 threads (8 warps), warp tile 64x32, K-chunk 64.
// 3-stage cp.async pipeline (144KB smem: Ahi, Alo, W per stage).
// ROPE=true: fused RoPE + head-split epilogue (Q/K bf16 hi/lo, V fp16 hi/lo).
// ---------------------------------------------------------------------------
#define GK_TILE   16384                 // 128 rows x 128B (64 fp16)
#define GK_STAGE  (3*GK_TILE)           // Ahi, Alo, W = 48KB
#define GK_NST    3
#define GK_SMEM   (GK_NST*GK_STAGE)     // 144KB
#define NKCH      16

template<bool ROPE>
__global__ void __launch_bounds__(256, 1) gemm_hmma(
    const __half* __restrict__ Ahi, const __half* __restrict__ Alo,
    const __half* __restrict__ W,
    const int* __restrict__ pos, float* __restrict__ C)
{
    extern __shared__ char smem[];
    const uint32_t sbase = smem_u32(smem);
    const int tid = threadIdx.x, lane = tid & 31, wid = tid >> 5;
    const int n0 = blockIdx.x * 128, m0 = blockIdx.y * 128, z = blockIdx.z;

    const __half* __restrict__ srcs[3] = {
        Ahi + (size_t)m0 * DM,
        Alo + (size_t)m0 * DM,
        W + (size_t)z * DM * DM + (size_t)n0 * DM };

    auto fill = [&](int st, int kt) {
        uint32_t sb = sbase + st * GK_STAGE;
        #pragma unroll
        for (int t = 0; t < 3; t++) {
            const __half* s = srcs[t] + kt * 64;
            #pragma unroll
            for (int j = 0; j < 4; j++) {
                int idx = j * 256 + tid;
                int row = idx >> 3, cu = idx & 7;
                cp16(sb + t * GK_TILE + SWZ((uint32_t)(row * 128 + cu * 16)),
                     s + (size_t)row * DM + cu * 8);
            }
        }
        cp_commit();
    };

    const int wm = (wid & 1) * 64;
    const int wn = (wid >> 1) * 32;
    const int a_row = lane & 15;
    const int a_ku  = lane >> 4;
    const int b_row = ((lane >> 4) << 3) + (lane & 7);
    const int b_ku  = (lane >> 3) & 1;

    float acc[4][4][4];
    #pragma unroll
    for (int i = 0; i < 4; i++)
        #pragma unroll
        for (int j = 0; j < 4; j++)
            #pragma unroll
            for (int c = 0; c < 4; c++) acc[i][j][c] = 0.0f;

    fill(0, 0);
    fill(1, 1);

    uint32_t ah[2][4][4], al[2][4][4], bf[2][2][4];

    int st = 0;
    #pragma unroll 1
    for (int kt = 0; kt < NKCH; kt++) {
        if (kt == NKCH - 1) cp_wait<0>(); else cp_wait<1>();
        __syncthreads();

        if (kt + 2 < NKCH) {
            int fs = st + 2; if (fs >= GK_NST) fs -= GK_NST;
            fill(fs, kt + 2);
        }

        const uint32_t sb  = sbase + st * GK_STAGE;
        const uint32_t sAh = sb, sAl = sb + GK_TILE, sB = sb + 2*GK_TILE;

        gemm_ldfrag(sAh, sAl, sB, wm, wn, a_row, a_ku, b_row, b_ku, 0,
                    ah[0], al[0], bf[0]);

        #pragma unroll
        for (int q = 0; q < 4; q++) {
            const int cur = q & 1, nxt = cur ^ 1;
            if (q < 3)
                gemm_ldfrag(sAh, sAl, sB, wm, wn, a_row, a_ku, b_row, b_ku, q + 1,
                            ah[nxt], al[nxt], bf[nxt]);
            #pragma unroll
            for (int i = 0; i < 4; i++)
                #pragma unroll
                for (int jj = 0; jj < 4; jj++) {
                    const int j16 = jj >> 1, h = (jj & 1) * 2;
                    mma16816h(acc[i][jj], ah[cur][i], bf[cur][j16][h], bf[cur][j16][h+1]);
                    mma16816h(acc[i][jj], al[cur][i], bf[cur][j16][h], bf[cur][j16][h+1]);
                }
        }
        if (++st == GK_NST) st = 0;
    }

    const int er = lane >> 2;
    const int ec = (lane & 3) * 2;

    if constexpr (!ROPE) {
        #pragma unroll
        for (int i = 0; i < 4; i++)
            #pragma unroll
            for (int jj = 0; jj < 4; jj++) {
                const int row = m0 + wm + i*16 + er;
                const int col = n0 + wn + jj*8 + ec;
                *(float2*)(C + (size_t)row * DM + col)       = make_float2(acc[i][jj][0], acc[i][jj][1]);
                *(float2*)(C + (size_t)(row + 8) * DM + col) = make_float2(acc[i][jj][2], acc[i][jj][3]);
            }
    } else if (z == 2) {
        // V: no RoPE; head split + fp16 hi/lo
        #pragma unroll
        for (int i = 0; i < 4; i++) {
            #pragma unroll
            for (int half = 0; half < 2; half++) {
                const int row = m0 + wm + i*16 + er + half*8;   // global m = b*SS+s
                const int b = row >> 11, s = row & (SS - 1);
                #pragma unroll
                for (int jj = 0; jj < 4; jj++) {
                    const int col = n0 + wn + jj*8 + ec;
                    float e = acc[i][jj][half*2], o = acc[i][jj][half*2+1];
                    float eh = __half2float(__float2half_rn(e));
                    float oh = __half2float(__float2half_rn(o));
                    const int h = col >> 6, d = col & 63;
                    size_t di = ((size_t)((b << 4) + h) * SS + s) * HD + d;
                    *(uint32_t*)(g_vhi + di) = pack_f16(e, o);
                    *(uint32_t*)(g_vlo + di) = pack_f16(e - eh, o - oh);
                }
            }
        }
    } else {
        // Q/K: fused RoPE + head split + bf16 hi/lo
        __nv_bfloat16* hiA = (z == 0) ? g_qhi : g_khi;
        __nv_bfloat16* loA = (z == 0) ? g_qlo : g_klo;
        float ifr[4];
        #pragma unroll
        for (int jj = 0; jj < 4; jj++) {
            int dcol = (wn & 32) + jj*8 + ec;        // even d index within head
            ifr[jj] = __expf(-(float)dcol * (9.210340371976184f / 64.0f));
        }
        #pragma unroll
        for (int i = 0; i < 4; i++) {
            #pragma unroll
            for (int half = 0; half < 2; half++) {
                const int row = m0 + wm + i*16 + er + half*8;   // global m = b*SS+s
                const int b = row >> 11, s = row & (SS - 1);
                const int ps = pos[row];
                #pragma unroll
                for (int jj = 0; jj < 4; jj++) {
                    const int col = n0 + wn + jj*8 + ec;
                    float e = acc[i][jj][half*2], o = acc[i][jj][half*2+1];
                    float sn, cs;
                    sincosf((float)ps * ifr[jj], &sn, &cs);
                    float e2 = e * cs - o * sn;
                    o        = e * sn + o * cs;
                    e = e2;
                    float eh = __bfloat162float(__float2bfloat16_rn(e));
                    float oh = __bfloat162float(__float2bfloat16_rn(o));
                    const int h = col >> 6, d = col & 63;
                    size_t di = ((size_t)((b << 4) + h) * SS + s) * HD + d;
                    *(uint32_t*)(hiA + di) = pack_bf16(eh, oh);
                    *(uint32_t*)(loA + di) = pack_bf16(e - eh, o - oh);
                }
            }
        }
    }
}

// ---------------------------------------------------------------------------
// Attention fragment loaders
// ---------------------------------------------------------------------------
__device__ __forceinline__ void attn_ldK(uint32_t sKh, uint32_t sKl,
                                         int b_row, int b_ku, int st,
                                         uint32_t kh[4][4], uint32_t kl[4][4])
{
    const int cu = st * 2;
    #pragma unroll
    for (int jn = 0; jn < 4; jn++) {
        uint32_t off = SWZ((uint32_t)((jn*16 + b_row) * 128 + (cu + b_ku) * 16));
        ldsm4(sKh + off, kh[jn]);
        ldsm4(sKl + off, kl[jn]);
    }
}
__device__ __forceinline__ void attn_ldV(uint32_t sVh, uint32_t sVl,
                                         int v_row, int v_cb, int kk,
                                         uint32_t vh[4][4], uint32_t vl[4][4])
{
    #pragma unroll
    for (int jv = 0; jv < 4; jv++) {
        uint32_t off = SWZ((uint32_t)((kk*16 + v_row) * 128 + jv*32 + v_cb));
        ldsm4t(sVh + off, vh[jv]);
        ldsm4t(sVl + off, vl[jv]);
    }
}

// ---------------------------------------------------------------------------
// HMMA flash attention (round-11 proven version): 64 query rows per CTA,
// 4 warps, 2 CTAs/SM.  S = split-bf16 (3 MMAs); PV = fp16 P x fp16 V hi/lo (2).
// Output now written as fp16 hi/lo for the 2-term WO GEMM.
// ---------------------------------------------------------------------------
#define AQ_TILE 8192
#define AKV_TILE 8192
#define AKV_STAGE (4*AKV_TILE)
#define AKV_NST 3
#define ASMEM (2*AQ_TILE + AKV_NST*AKV_STAGE)   // 112KB

__global__ void __launch_bounds__(128, 2) attn_hmma()
{
    extern __shared__ char smem[];
    const uint32_t sbase = smem_u32(smem);
    const int tid = threadIdx.x, lane = tid & 31, wid = tid >> 5;   // wid 0..3
    const int qt = (int)gridDim.x - 1 - (int)blockIdx.x;            // long first
    const int bh = blockIdx.y;
    const int s0 = qt * 64;
    const int nkt = qt + 1;

    const size_t bhoff = (size_t)bh * SS * HD;
    const __nv_bfloat16* Qh = g_qhi + bhoff + (size_t)s0 * HD;
    const __nv_bfloat16* Ql = g_qlo + bhoff + (size_t)s0 * HD;
    const __nv_bfloat16* kvsrc[4] = {
        g_khi + bhoff, g_klo + bhoff,
        reinterpret_cast<const __nv_bfloat16*>(g_vhi) + bhoff,
        reinterpret_cast<const __nv_bfloat16*>(g_vlo) + bhoff };

    const uint32_t sQ  = sbase;
    const uint32_t sKV = sbase + 2*AQ_TILE;

    {   // Q hi/lo: 64 rows x 8 16B-units each
        #pragma unroll
        for (int j = 0; j < 4; j++) {
            int idx = j * 128 + tid;
            int row = idx >> 3, cu = idx & 7;
            uint32_t off = SWZ((uint32_t)(row * 128 + cu * 16));
            cp16(sQ + off,           Qh + (size_t)row * HD + cu * 8);
            cp16(sQ + AQ_TILE + off, Ql + (size_t)row * HD + cu * 8);
        }
        cp_commit();
    }
    auto fill_kv = [&](int st, int kb) {
        uint32_t sb = sKV + st * AKV_STAGE;
        #pragma unroll
        for (int t = 0; t < 4; t++) {
            const __nv_bfloat16* s = kvsrc[t] + (size_t)kb * 64 * HD;
            #pragma unroll
            for (int r = 0; r < 4; r++) {
                int idx = r * 128 + tid;
                int row = idx >> 3, cu = idx & 7;
                cp16(sb + t * AKV_TILE + SWZ((uint32_t)(row * 128 + cu * 16)),
                     s + (size_t)row * HD + cu * 8);
            }
        }
        cp_commit();
    };
    fill_kv(0, 0);
    if (nkt > 1) fill_kv(1, 1); else cp_commit();   // keep group count consistent

    cp_wait<2>();
    __syncthreads();
    uint32_t qh[4][4], ql[4][4];
    {
        const int a_row = lane & 15, a_ku = lane >> 4;
        #pragma unroll
        for (int st = 0; st < 4; st++) {
            uint32_t off = SWZ((uint32_t)((wid*16 + a_row) * 128 + (st*2 + a_ku) * 16));
            ldsm4(sQ + off, qh[st]);
            ldsm4(sQ + AQ_TILE + off, ql[st]);
        }
    }

    float o_acc[8][4];
    #pragma unroll
    for (int jj = 0; jj < 8; jj++)
        #pragma unroll
        for (int c = 0; c < 4; c++) o_acc[jj][c] = 0.0f;
    float row_max[2] = {-1e30f, -1e30f}, row_l[2] = {0.0f, 0.0f};

    const int b_row = ((lane >> 4) << 3) + (lane & 7);
    const int b_ku  = (lane >> 3) & 1;
    const int v_row = lane & 15;
    const int v_cb  = ((lane >> 4) << 3) * 2;
    const float scale = 0.125f;

    int stg = 0;
    #pragma unroll 1
    for (int kb = 0; kb < nkt; kb++) {
        if (kb == nkt - 1) cp_wait<0>(); else cp_wait<1>();
        __syncthreads();

        if (kb + 2 < nkt) {
            int fs = stg + 2; if (fs >= AKV_NST) fs -= AKV_NST;
            fill_kv(fs, kb + 2);
        }

        const uint32_t sb = sKV + stg * AKV_STAGE;
        const uint32_t sKh = sb, sKl = sb + AKV_TILE;
        const uint32_t sVh = sb + 2*AKV_TILE, sVl = sb + 3*AKV_TILE;

        // ---- S = Q K^T (split-bf16, 3 MMAs) ----
        float sacc[8][4];
        #pragma unroll
        for (int jj = 0; jj < 8; jj++)
            #pragma unroll
            for (int c = 0; c < 4; c++) sacc[jj][c] = 0.0f;

        uint32_t kh[2][4][4], kl[2][4][4];
        attn_ldK(sKh, sKl, b_row, b_ku, 0, kh[0], kl[0]);
        #pragma unroll
        for (int st = 0; st < 4; st++) {
            const int cur = st & 1, nxt = cur ^ 1;
            if (st < 3)
                attn_ldK(sKh, sKl, b_row, b_ku, st + 1, kh[nxt], kl[nxt]);
            #pragma unroll
            for (int jj = 0; jj < 8; jj++) {
                const int j16 = jj >> 1, h = (jj & 1) * 2;
                mma16816(sacc[jj], qh[st], kh[cur][j16][h], kh[cur][j16][h+1]);
                mma16816(sacc[jj], qh[st], kl[cur][j16][h], kl[cur][j16][h+1]);
                mma16816(sacc[jj], ql[st], kh[cur][j16][h], kh[cur][j16][h+1]);
            }
        }

        // ---- prefetch V fragments for kk=0 (overlaps softmax ALU) ----
        uint32_t vh[2][4][4], vl[2][4][4];
        attn_ldV(sVh, sVl, v_row, v_cb, 0, vh[0], vl[0]);

        // ---- online softmax ----
        const bool tmask = (kb == qt);
        #pragma unroll
        for (int rh = 0; rh < 2; rh++) {
            const int grow = s0 + wid*16 + (lane >> 2) + rh*8;
            float mx = -1e30f;
            #pragma unroll
            for (int jj = 0; jj < 8; jj++)
                #pragma unroll
                for (int dc = 0; dc < 2; dc++) {
                    float v = sacc[jj][rh*2+dc] * scale;
                    if (tmask && (kb*64 + jj*8 + 2*(lane&3) + dc > grow)) v = -1e30f;
                    sacc[jj][rh*2+dc] = v;
                    mx = fmaxf(mx, v);
                }
            mx = fmaxf(mx, __shfl_xor_sync(0xffffffffu, mx, 1));
            mx = fmaxf(mx, __shfl_xor_sync(0xffffffffu, mx, 2));
            float mnew = fmaxf(row_max[rh], mx);
            float corr = __expf(row_max[rh] - mnew);
            row_max[rh] = mnew;
            float sum = 0.0f;
            #pragma unroll
            for (int jj = 0; jj < 8; jj++)
                #pragma unroll
                for (int dc = 0; dc < 2; dc++) {
                    float pv = __expf(sacc[jj][rh*2+dc] - mnew);
                    sacc[jj][rh*2+dc] = pv;
                    sum += pv;
                }
            sum += __shfl_xor_sync(0xffffffffu, sum, 1);
            sum += __shfl_xor_sync(0xffffffffu, sum, 2);
            row_l[rh] = row_l[rh] * corr + sum;
            #pragma unroll
            for (int jj = 0; jj < 8; jj++) {
                o_acc[jj][rh*2]   *= corr;
                o_acc[jj][rh*2+1] *= corr;
            }
        }

        // ---- O += P V  (P fp16 single, V fp16 hi/lo: 2 MMAs) ----
        #pragma unroll
        for (int kk = 0; kk < 4; kk++) {
            const int cur = kk & 1, nxt = cur ^ 1;
            if (kk < 3)
                attn_ldV(sVh, sVl, v_row, v_cb, kk + 1, vh[nxt], vl[nxt]);
            uint32_t ph[4];
            #pragma unroll
            for (int u = 0; u < 4; u++) {
                const int jj = 2*kk + (u >> 1), cb = (u & 1) * 2;
                ph[u] = pack_f16(sacc[jj][cb], sacc[jj][cb+1]);
            }
            #pragma unroll
            for (int jj = 0; jj < 8; jj++) {
                const int j16 = jj >> 1, h = (jj & 1) * 2;
                mma16816h(o_acc[jj], ph, vh[cur][j16][h], vh[cur][j16][h+1]);
                mma16816h(o_acc[jj], ph, vl[cur][j16][h], vl[cur][j16][h+1]);
            }
        }
        if (++stg == AKV_NST) stg = 0;
    }

    const int b = bh >> 4, h = bh & 15;
    const float inv0 = 1.0f / row_l[0], inv1 = 1.0f / row_l[1];
    #pragma unroll
    for (int jj = 0; jj < 8; jj++) {
        #pragma unroll
        for (int rh = 0; rh < 2; rh++) {
            const int row = s0 + wid*16 + (lane >> 2) + rh*8;
            const int d   = jj*8 + 2*(lane & 3);
            const float inv = rh ? inv1 : inv0;
            float x = o_acc[jj][rh*2] * inv, y = o_acc[jj][rh*2+1] * inv;
            float hx = __half2float(__float2half_rn(x));
            float hy = __half2float(__float2half_rn(y));
            size_t di = ((size_t)(b * SS + row)) * DM + h * HD + d;
            *(uint32_t*)(g_xhi + di) = pack_f16(x, y);
            *(uint32_t*)(g_xlo + di) = pack_f16(x - hx, y - hy);
        }
    }
}

// ---------------------------------------------------------------------------
extern "C" void kernel_launch(void* const* d_in, const int* in_sizes, int n_in,
                              void* d_out, int out_size)
{
    const float* x  = (const float*)d_in[0];
    const int*  pos = (const int*)  d_in[1];
    const float* wq = (const float*)d_in[2];
    const float* wk = (const float*)d_in[3];
    const float* wv = (const float*)d_in[4];
    const float* wo = (const float*)d_in[5];
    float* out = (float*)d_out;

    void* p;
    cudaGetSymbolAddress(&p, g_xhi);   __half* xhi = (__half*)p;
    cudaGetSymbolAddress(&p, g_xlo);   __half* xlo = (__half*)p;
    cudaGetSymbolAddress(&p, g_w);     __half* w   = (__half*)p;

    cudaFuncSetAttribute(gemm_hmma<true>,  cudaFuncAttributeMaxDynamicSharedMemorySize, GK_SMEM);
    cudaFuncSetAttribute(gemm_hmma<false>, cudaFuncAttributeMaxDynamicSharedMemorySize, GK_SMEM);
    cudaFuncSetAttribute(attn_hmma, cudaFuncAttributeMaxDynamicSharedMemorySize, ASMEM);

    // 0) convert x -> fp16 hi/lo, weights -> single fp16
    conv_hilo<<<(BSD/4 + 255)/256, 256>>>((const float4*)x, xhi, xlo, BSD/4);
    conv_w<<<dim3(DM*DM/4/256, 4), 256>>>((const float4*)wq, (const float4*)wk,
                                          (const float4*)wv, (const float4*)wo);

    // 1) q,k,v = x @ {wq,wk,wv}^T with fused RoPE + head split
    //    -> q,k bf16 hi/lo, v fp16 hi/lo
    gemm_hmma<true><<<dim3(DM/128, MT/128, 3), 256, GK_SMEM>>>(xhi, xlo, w, pos, nullptr);

    // 2) HMMA flash attention (64-row CTAs, 2/SM) -> g_xhi/g_xlo (fp16 hi/lo)
    attn_hmma<<<dim3(SS/64, BB*NH), 128, ASMEM>>>();

    // 3) out = attn @ wo^T
    gemm_hmma<false><<<dim3(DM/128, MT/128, 1), 256, GK_SMEM>>>(
        xhi, xlo, w + 3*(size_t)DM*DM, nullptr, out);
}